// round 10
// baseline (speedup 1.0000x reference)
#include <cuda_runtime.h>
#include <cuda_bf16.h>
#include <math.h>
#include <stdint.h>

// Problem constants
#define B_     8
#define T_     512
#define C_     512
#define L_     4
#define NH_    8
#define DH_    64
#define S_     1024
#define MROWS  8192
#define FF_    2048
#define SD_    48
#define AD_    12

typedef __nv_bfloat16 bf16;

// ---------------------------------------------------------------------------
// Static scratch
// ---------------------------------------------------------------------------
__device__ float g_H  [MROWS * C_];
__device__ float g_tmp[MROWS * C_];

__device__ bf16 g_Hhi [MROWS * C_],  g_Hlo [MROWS * C_];
__device__ bf16 g_ATThi[MROWS * C_], g_ATTlo[MROWS * C_];
__device__ bf16 g_FFhi[MROWS * FF_], g_FFlo[MROWS * FF_];

__device__ bf16 g_qhi[MROWS * C_], g_qlo[MROWS * C_];
__device__ bf16 g_khi[MROWS * C_], g_klo[MROWS * C_];
__device__ bf16 g_vhi[MROWS * C_], g_vlo[MROWS * C_];

#define OW_Q 0
#define OW_K (L_ * C_ * C_)
#define OW_V (2 * L_ * C_ * C_)
#define OW_O (3 * L_ * C_ * C_)
#define OW_1 (4 * L_ * C_ * C_)
#define OW_2 (4 * L_ * C_ * C_ + L_ * FF_ * C_)
#define WTOT (4 * L_ * C_ * C_ + 2 * L_ * FF_ * C_)
__device__ bf16 g_Whi[WTOT], g_Wlo[WTOT];

// ---------------------------------------------------------------------------
// PTX helpers (sm_80-era, valid on plain sm_100 target)
// ---------------------------------------------------------------------------
__device__ __forceinline__ uint32_t smem_u32(const void* p) {
    uint32_t a;
    asm("{ .reg .u64 t; cvta.to.shared.u64 t, %1; cvt.u32.u64 %0, t; }"
        : "=r"(a) : "l"(p));
    return a;
}

#define CP16(dst, src) \
    asm volatile("cp.async.cg.shared.global [%0], [%1], 16;" \
                 :: "r"(dst), "l"(src) : "memory")
#define CP_COMMIT()  asm volatile("cp.async.commit_group;" ::: "memory")
#define CP_WAIT1()   asm volatile("cp.async.wait_group 1;" ::: "memory")
#define CP_WAIT0()   asm volatile("cp.async.wait_group 0;" ::: "memory")

#define LDM_X4(r0, r1, r2, r3, addr) \
    asm volatile("ldmatrix.sync.aligned.m8n8.x4.shared.b16 {%0,%1,%2,%3}, [%4];" \
                 : "=r"(r0), "=r"(r1), "=r"(r2), "=r"(r3) : "r"(addr))

#define LDM_X4_T(r0, r1, r2, r3, addr) \
    asm volatile("ldmatrix.sync.aligned.m8n8.x4.trans.shared.b16 {%0,%1,%2,%3}, [%4];" \
                 : "=r"(r0), "=r"(r1), "=r"(r2), "=r"(r3) : "r"(addr))

#define MMA_BF16(c, a, b) \
    asm volatile("mma.sync.aligned.m16n8k16.row.col.f32.bf16.bf16.f32 " \
                 "{%0,%1,%2,%3}, {%4,%5,%6,%7}, {%8,%9}, {%0,%1,%2,%3};" \
                 : "+f"((c)[0]), "+f"((c)[1]), "+f"((c)[2]), "+f"((c)[3]) \
                 : "r"((a)[0]), "r"((a)[1]), "r"((a)[2]), "r"((a)[3]), \
                   "r"((b)[0]), "r"((b)[1]))

__device__ __forceinline__ void split2(float v, bf16& h, bf16& l) {
    h = __float2bfloat16(v);
    l = __float2bfloat16(v - __bfloat162float(h));
}

__device__ __forceinline__ void packsplit(float a, float b, uint32_t& ph, uint32_t& pl) {
    __nv_bfloat162 h2, l2;
    bf16 ha, la, hb, lb;
    split2(a, ha, la); split2(b, hb, lb);
    h2.x = ha; h2.y = hb; l2.x = la; l2.y = lb;
    ph = *(uint32_t*)&h2; pl = *(uint32_t*)&l2;
}

// ---------------------------------------------------------------------------
// Merged fp32 -> (hi, lo) bf16 converter for all six weight groups
// ---------------------------------------------------------------------------
#define CS_Q (L_ * C_ * C_ / 4)
#define CS_W1 (L_ * FF_ * C_ / 4)
#define CTOT4 (4 * CS_Q + 2 * CS_W1)

__global__ __launch_bounds__(256) void convert6_kernel(
    const float* __restrict__ Wq, const float* __restrict__ Wk,
    const float* __restrict__ Wv, const float* __restrict__ Wo,
    const float* __restrict__ W1, const float* __restrict__ W2,
    bf16* __restrict__ hi, bf16* __restrict__ lo)
{
    for (int i = blockIdx.x * 256 + threadIdx.x; i < CTOT4; i += gridDim.x * 256) {
        const float* src;
        int li;
        if      (i < CS_Q)      { src = Wq; li = i; }
        else if (i < 2 * CS_Q)  { src = Wk; li = i - CS_Q; }
        else if (i < 3 * CS_Q)  { src = Wv; li = i - 2 * CS_Q; }
        else if (i < 4 * CS_Q)  { src = Wo; li = i - 3 * CS_Q; }
        else if (i < 4 * CS_Q + CS_W1) { src = W1; li = i - 4 * CS_Q; }
        else                    { src = W2; li = i - 4 * CS_Q - CS_W1; }
        float4 v = ((const float4*)src)[li];
        uint32_t h01, l01, h23, l23;
        packsplit(v.x, v.y, h01, l01);
        packsplit(v.z, v.w, h23, l23);
        ((uint2*)hi)[i] = make_uint2(h01, h23);
        ((uint2*)lo)[i] = make_uint2(l01, l23);
    }
}

// ---------------------------------------------------------------------------
// Tensor-core GEMM via mma.sync, split-bf16 (hh + hl + lh), 2 CTAs/SM.
// ---------------------------------------------------------------------------
#define RS_B    80
#define TILE_B  (128 * RS_B)
#define STAGE_B (4 * TILE_B)
#define DSMEM_SZ (2 * STAGE_B)

__device__ __forceinline__ void issue_stage(
    const bf16* __restrict__ Ahi, const bf16* __restrict__ Alo,
    const bf16* __restrict__ Bhi, const bf16* __restrict__ Blo,
    int m0, int n0, int K, int k0, uint32_t sstage, int tid)
{
#pragma unroll
    for (int it = 0; it < 8; it++) {
        int id  = tid + it * 256;
        int mat = id >> 9;
        int rem = id & 511;
        int r   = rem >> 2;
        int c   = rem & 3;
        const bf16* src = (mat == 0) ? Ahi : (mat == 1) ? Alo : (mat == 2) ? Bhi : Blo;
        int rowbase = (mat < 2) ? m0 : n0;
        const bf16* gp = src + (size_t)(rowbase + r) * K + k0 + c * 8;
        uint32_t dst = sstage + mat * TILE_B + r * RS_B + c * 16;
        CP16(dst, gp);
    }
    CP_COMMIT();
}

__device__ __forceinline__ void tc_gemm_body(
    const bf16* __restrict__ Ahi, const bf16* __restrict__ Alo,
    const bf16* __restrict__ Bhi, const bf16* __restrict__ Blo,
    const float* __restrict__ bias, const float* __restrict__ resid,
    float* __restrict__ outF, bf16* __restrict__ outHi, bf16* __restrict__ outLo,
    int Nn, int K, int gelu, int headLayout, float oscale, int bx, int by)
{
    extern __shared__ char dsm[];
    uint32_t sbase = smem_u32(dsm);

    int tid  = threadIdx.x;
    int lane = tid & 31;
    int wid  = tid >> 5;
    int wm0  = (wid & 3) * 32;
    int wn0  = (wid >> 2) * 64;
    int m0   = by * 128;
    int n0   = bx * 128;

    float acc[2][8][4];
#pragma unroll
    for (int mt = 0; mt < 2; mt++)
#pragma unroll
        for (int nf = 0; nf < 8; nf++)
#pragma unroll
            for (int e = 0; e < 4; e++) acc[mt][nf][e] = 0.f;

    int S = K >> 5;

    issue_stage(Ahi, Alo, Bhi, Blo, m0, n0, K, 0, sbase, tid);

    int aRow = wm0 + (lane & 15);
    int aColB = ((lane >> 4) * 8) * 2;
    int bRowOff = (lane & 7) + ((lane >> 4) << 3);
    int bColB = (((lane >> 3) & 1) * 8) * 2;

    for (int s = 0; s < S; s++) {
        if (s + 1 < S) {
            issue_stage(Ahi, Alo, Bhi, Blo, m0, n0, K, (s + 1) << 5,
                        sbase + ((s + 1) & 1) * STAGE_B, tid);
            CP_WAIT1();
        } else {
            CP_WAIT0();
        }
        __syncthreads();

        uint32_t st  = sbase + (s & 1) * STAGE_B;
        uint32_t sAh = st;
        uint32_t sAl = st + TILE_B;
        uint32_t sBh = st + 2 * TILE_B;
        uint32_t sBl = st + 3 * TILE_B;

#pragma unroll
        for (int kk = 0; kk < 2; kk++) {
            uint32_t kByte = kk * 32;

            uint32_t ah[2][4], al[2][4];
#pragma unroll
            for (int mt = 0; mt < 2; mt++) {
                uint32_t addr = sAh + (aRow + mt * 16) * RS_B + kByte + aColB;
                LDM_X4(ah[mt][0], ah[mt][1], ah[mt][2], ah[mt][3], addr);
                addr = sAl + (aRow + mt * 16) * RS_B + kByte + aColB;
                LDM_X4(al[mt][0], al[mt][1], al[mt][2], al[mt][3], addr);
            }

#pragma unroll
            for (int nt = 0; nt < 4; nt++) {
                uint32_t bh0[2], bh1[2], bl0[2], bl1[2];
                uint32_t addr = sBh + (wn0 + nt * 16 + bRowOff) * RS_B + kByte + bColB;
                LDM_X4(bh0[0], bh0[1], bh1[0], bh1[1], addr);
                addr = sBl + (wn0 + nt * 16 + bRowOff) * RS_B + kByte + bColB;
                LDM_X4(bl0[0], bl0[1], bl1[0], bl1[1], addr);
#pragma unroll
                for (int mt = 0; mt < 2; mt++) {
                    MMA_BF16(acc[mt][2 * nt],     ah[mt], bh0);
                    MMA_BF16(acc[mt][2 * nt],     ah[mt], bl0);
                    MMA_BF16(acc[mt][2 * nt],     al[mt], bh0);
                    MMA_BF16(acc[mt][2 * nt + 1], ah[mt], bh1);
                    MMA_BF16(acc[mt][2 * nt + 1], ah[mt], bl1);
                    MMA_BF16(acc[mt][2 * nt + 1], al[mt], bh1);
                }
            }
        }
        __syncthreads();
    }

    // epilogue
#pragma unroll
    for (int mt = 0; mt < 2; mt++) {
#pragma unroll
        for (int rr = 0; rr < 2; rr++) {
            int m = m0 + wm0 + mt * 16 + (lane >> 2) + rr * 8;
#pragma unroll
            for (int nf = 0; nf < 8; nf++) {
                int c0 = n0 + wn0 + nf * 8 + (lane & 3) * 2;
                float v0 = (acc[mt][nf][rr * 2 + 0] + bias[c0]) * oscale;
                float v1 = (acc[mt][nf][rr * 2 + 1] + bias[c0 + 1]) * oscale;
                if (resid) {
                    const float2 rv = *(const float2*)(resid + (size_t)m * Nn + c0);
                    v0 += rv.x; v1 += rv.y;
                }
                if (gelu) {
                    v0 = 0.5f * v0 * (1.f + erff(v0 * 0.70710678118654752f));
                    v1 = 0.5f * v1 * (1.f + erff(v1 * 0.70710678118654752f));
                }
                if (outF) {
                    float* dst;
                    if (headLayout) {
                        int bb = m >> 10, sR = m & 1023, hd = c0 >> 6, d0 = c0 & 63;
                        dst = outF + (((size_t)(bb * NH_ + hd) * S_) + sR) * DH_ + d0;
                    } else {
                        dst = outF + (size_t)m * Nn + c0;
                    }
                    *(float2*)dst = make_float2(v0, v1);
                } else {
                    size_t off;
                    if (headLayout) {
                        int bb = m >> 10, sR = m & 1023, hd = c0 >> 6, d0 = c0 & 63;
                        off = (((size_t)(bb * NH_ + hd) * S_) + sR) * DH_ + d0;
                    } else {
                        off = (size_t)m * Nn + c0;
                    }
                    uint32_t ph, pl;
                    packsplit(v0, v1, ph, pl);
                    *(uint32_t*)(outHi + off) = ph;
                    *(uint32_t*)(outLo + off) = pl;
                }
            }
        }
    }
}

__global__ __launch_bounds__(256, 2) void tc_gemm_kernel(
    const bf16* Ahi, const bf16* Alo, const bf16* Bhi, const bf16* Blo,
    const float* bias, const float* resid,
    float* outF, bf16* outHi, bf16* outLo,
    int Nn, int K, int gelu, int headLayout)
{
    tc_gemm_body(Ahi, Alo, Bhi, Blo, bias, resid, outF, outHi, outLo,
                 Nn, K, gelu, headLayout, 1.0f, blockIdx.x, blockIdx.y);
}

// Fused Q/K/V: grid.x = 12; outputs split bf16 head-layout; Q scaled by 0.125.
__global__ __launch_bounds__(256, 2) void tc_qkv_kernel(
    const bf16* Ahi, const bf16* Alo,
    const bf16* Wqh, const bf16* Wql, const float* bq,
    const bf16* Wkh, const bf16* Wkl, const float* bk,
    const bf16* Wvh, const bf16* Wvl, const float* bv,
    bf16* qhi, bf16* qlo, bf16* khi, bf16* klo, bf16* vhi, bf16* vlo)
{
    int which = blockIdx.x >> 2;
    int bx    = blockIdx.x & 3;
    const bf16* Bh  = (which == 0) ? Wqh : (which == 1) ? Wkh : Wvh;
    const bf16* Bl  = (which == 0) ? Wql : (which == 1) ? Wkl : Wvl;
    const float* bi = (which == 0) ? bq  : (which == 1) ? bk  : bv;
    bf16* oh        = (which == 0) ? qhi : (which == 1) ? khi : vhi;
    bf16* ol        = (which == 0) ? qlo : (which == 1) ? klo : vlo;
    float sc        = (which == 0) ? 0.125f : 1.0f;
    tc_gemm_body(Ahi, Alo, Bh, Bl, bi, nullptr, nullptr, oh, ol,
                 C_, C_, 0, 1, sc, bx, blockIdx.y);
}

// ---------------------------------------------------------------------------
// Tensor-core causal flash attention, v2:
//   128-row Q tile, 8 warps, cp.async double-buffered K/V, 2 CTAs/SM.
//   Smem: 2 x 36864-byte buffers; Q (hi+lo) initially lives in buffer 1 and
//   is overwritten by the K/V pipeline after Q fragments are in registers.
// ---------------------------------------------------------------------------
#define RSA_B   144                 // 64 bf16 row padded to 72 (144 bytes)
#define ATT_ARR (64 * RSA_B)        // 9216: one 64x64 bf16 array
#define ATT_BUF (4 * ATT_ARR)       // 36864: KH,KL,VH,VL for one stage
#define ATT_SMEM (2 * ATT_BUF)      // 73728

__device__ __forceinline__ void attn_prefetch(
    const bf16* __restrict__ Khi, const bf16* __restrict__ Klo,
    const bf16* __restrict__ Vhi, const bf16* __restrict__ Vlo,
    size_t base, int k0, uint32_t bufb, int tid)
{
    int arr = tid >> 6;          // 0..3 -> KH,KL,VH,VL
    int row = tid & 63;
    const bf16* src = ((arr == 0) ? Khi : (arr == 1) ? Klo : (arr == 2) ? Vhi : Vlo)
                      + base + (size_t)(k0 + row) * DH_;
    uint32_t dst = bufb + arr * ATT_ARR + row * RSA_B;
#pragma unroll
    for (int i = 0; i < 8; i++) CP16(dst + i * 16, src + i * 8);
}

__global__ __launch_bounds__(256, 2) void attn_tc_kernel(
    const bf16* __restrict__ Qhi, const bf16* __restrict__ Qlo,
    const bf16* __restrict__ Khi, const bf16* __restrict__ Klo,
    const bf16* __restrict__ Vhi, const bf16* __restrict__ Vlo,
    bf16* __restrict__ attHi, bf16* __restrict__ attLo)
{
    extern __shared__ char sm[];
    uint32_t sb = smem_u32(sm);

    int tid  = threadIdx.x;
    int lane = tid & 31;
    int wid  = tid >> 5;           // 0..7, warp handles q rows [wid*16, wid*16+16)
    int head = blockIdx.y;
    int q0   = blockIdx.x * 128;
    size_t base = (size_t)head * S_ * DH_;

    // ---- load Q (hi+lo) into buffer 1 via cp.async ----
    {
        int arr = tid >> 7;        // 0: hi, 1: lo
        int row = tid & 127;
        const bf16* src = (arr ? Qlo : Qhi) + base + (size_t)(q0 + row) * DH_;
        uint32_t dst = sb + ATT_BUF + arr * (128 * RSA_B / 2) * 0 + arr * 18432 + row * RSA_B;
#pragma unroll
        for (int i = 0; i < 8; i++) CP16(dst + i * 16, src + i * 8);
        CP_COMMIT();
    }
    CP_WAIT0();
    __syncthreads();

    // ---- Q fragments into registers (4 k-chunks over d=64) ----
    int aRow = wid * 16 + (lane & 15);
    int aCol = (lane >> 4) * 16;
    uint32_t qh[4][4], ql[4][4];
#pragma unroll
    for (int kc = 0; kc < 4; kc++) {
        uint32_t addr = sb + ATT_BUF + aRow * RSA_B + kc * 32 + aCol;
        LDM_X4(qh[kc][0], qh[kc][1], qh[kc][2], qh[kc][3], addr);
        addr = sb + ATT_BUF + 18432 + aRow * RSA_B + kc * 32 + aCol;
        LDM_X4(ql[kc][0], ql[kc][1], ql[kc][2], ql[kc][3], addr);
    }
    __syncthreads();   // all warps done reading Q smem before stage-1 overwrites

    int nTiles = 2 * blockIdx.x + 2;

    // prefetch stages 0 and 1
    attn_prefetch(Khi, Klo, Vhi, Vlo, base, 0, sb, tid);
    CP_COMMIT();
    attn_prefetch(Khi, Klo, Vhi, Vlo, base, 64, sb + ATT_BUF, tid);
    CP_COMMIT();

    int bRow = (lane & 7) + ((lane >> 4) << 3);
    int bCol = ((lane >> 3) & 1) * 16;
    int vRow = (lane & 7) + (((lane >> 3) & 1) << 3);
    int vCol = (lane >> 4) * 16;

    float oa[8][4];
#pragma unroll
    for (int f = 0; f < 8; f++)
#pragma unroll
        for (int e = 0; e < 4; e++) oa[f][e] = 0.f;
    float m0r = -1e30f, m1r = -1e30f, l0r = 0.f, l1r = 0.f;

    for (int kt = 0; kt < nTiles; kt++) {
        int k0 = kt * 64;
        CP_WAIT1();
        __syncthreads();

        uint32_t bufb = sb + (kt & 1) * ATT_BUF;
        uint32_t sKH = bufb;
        uint32_t sKL = bufb + ATT_ARR;
        uint32_t sVH = bufb + 2 * ATT_ARR;
        uint32_t sVL = bufb + 3 * ATT_ARR;

        // ---- scores S = Q @ K^T (hh + hl + lh) ----
        float sc[8][4];
#pragma unroll
        for (int f = 0; f < 8; f++)
#pragma unroll
            for (int e = 0; e < 4; e++) sc[f][e] = 0.f;

#pragma unroll
        for (int kc = 0; kc < 4; kc++) {
#pragma unroll
            for (int ntk = 0; ntk < 4; ntk++) {
                uint32_t bh0[2], bh1[2], bl0[2], bl1[2];
                uint32_t addr = sKH + (ntk * 16 + bRow) * RSA_B + kc * 32 + bCol;
                LDM_X4(bh0[0], bh0[1], bh1[0], bh1[1], addr);
                addr = sKL + (ntk * 16 + bRow) * RSA_B + kc * 32 + bCol;
                LDM_X4(bl0[0], bl0[1], bl1[0], bl1[1], addr);
                MMA_BF16(sc[2 * ntk],     qh[kc], bh0);
                MMA_BF16(sc[2 * ntk],     qh[kc], bl0);
                MMA_BF16(sc[2 * ntk],     ql[kc], bh0);
                MMA_BF16(sc[2 * ntk + 1], qh[kc], bh1);
                MMA_BF16(sc[2 * ntk + 1], qh[kc], bl1);
                MMA_BF16(sc[2 * ntk + 1], ql[kc], bh1);
            }
        }

        // ---- causal mask (warp-uniform predicate) ----
        if (k0 + 63 > q0 + wid * 16) {
            int rg = q0 + wid * 16 + (lane >> 2);
#pragma unroll
            for (int f = 0; f < 8; f++) {
                int c = k0 + f * 8 + (lane & 3) * 2;
                if (c     > rg)     sc[f][0] = -1e30f;
                if (c + 1 > rg)     sc[f][1] = -1e30f;
                if (c     > rg + 8) sc[f][2] = -1e30f;
                if (c + 1 > rg + 8) sc[f][3] = -1e30f;
            }
        }

        // ---- online softmax ----
        float mx0 = -1e30f, mx1 = -1e30f;
#pragma unroll
        for (int f = 0; f < 8; f++) {
            mx0 = fmaxf(mx0, fmaxf(sc[f][0], sc[f][1]));
            mx1 = fmaxf(mx1, fmaxf(sc[f][2], sc[f][3]));
        }
        mx0 = fmaxf(mx0, __shfl_xor_sync(0xffffffffu, mx0, 1));
        mx0 = fmaxf(mx0, __shfl_xor_sync(0xffffffffu, mx0, 2));
        mx1 = fmaxf(mx1, __shfl_xor_sync(0xffffffffu, mx1, 1));
        mx1 = fmaxf(mx1, __shfl_xor_sync(0xffffffffu, mx1, 2));
        float mn0 = fmaxf(m0r, mx0);
        float mn1 = fmaxf(m1r, mx1);

        float sum0 = 0.f, sum1 = 0.f;
#pragma unroll
        for (int f = 0; f < 8; f++) {
            sc[f][0] = __expf(sc[f][0] - mn0);
            sc[f][1] = __expf(sc[f][1] - mn0);
            sc[f][2] = __expf(sc[f][2] - mn1);
            sc[f][3] = __expf(sc[f][3] - mn1);
            sum0 += sc[f][0] + sc[f][1];
            sum1 += sc[f][2] + sc[f][3];
        }
        sum0 += __shfl_xor_sync(0xffffffffu, sum0, 1);
        sum0 += __shfl_xor_sync(0xffffffffu, sum0, 2);
        sum1 += __shfl_xor_sync(0xffffffffu, sum1, 1);
        sum1 += __shfl_xor_sync(0xffffffffu, sum1, 2);

        float cr0 = __expf(m0r - mn0);
        float cr1 = __expf(m1r - mn1);
        l0r = l0r * cr0 + sum0;
        l1r = l1r * cr1 + sum1;
        m0r = mn0; m1r = mn1;
#pragma unroll
        for (int f = 0; f < 8; f++) {
            oa[f][0] *= cr0; oa[f][1] *= cr0;
            oa[f][2] *= cr1; oa[f][3] *= cr1;
        }

        // ---- O += P @ V ----
#pragma unroll
        for (int kc = 0; kc < 4; kc++) {
            uint32_t ph[4], pl[4];
            packsplit(sc[2 * kc][0],     sc[2 * kc][1],     ph[0], pl[0]);
            packsplit(sc[2 * kc][2],     sc[2 * kc][3],     ph[1], pl[1]);
            packsplit(sc[2 * kc + 1][0], sc[2 * kc + 1][1], ph[2], pl[2]);
            packsplit(sc[2 * kc + 1][2], sc[2 * kc + 1][3], ph[3], pl[3]);
#pragma unroll
            for (int nt = 0; nt < 4; nt++) {
                uint32_t vh0[2], vh1[2], vl0[2], vl1[2];
                uint32_t addr = sVH + (kc * 16 + vRow) * RSA_B + nt * 32 + vCol;
                LDM_X4_T(vh0[0], vh0[1], vh1[0], vh1[1], addr);
                addr = sVL + (kc * 16 + vRow) * RSA_B + nt * 32 + vCol;
                LDM_X4_T(vl0[0], vl0[1], vl1[0], vl1[1], addr);
                MMA_BF16(oa[2 * nt],     ph, vh0);
                MMA_BF16(oa[2 * nt],     ph, vl0);
                MMA_BF16(oa[2 * nt],     pl, vh0);
                MMA_BF16(oa[2 * nt + 1], ph, vh1);
                MMA_BF16(oa[2 * nt + 1], ph, vl1);
                MMA_BF16(oa[2 * nt + 1], pl, vh1);
            }
        }

        __syncthreads();   // all warps done with buffer (kt&1) before refill
        if (kt + 2 < nTiles)
            attn_prefetch(Khi, Klo, Vhi, Vlo, base, (kt + 2) * 64,
                          sb + (kt & 1) * ATT_BUF, tid);
        CP_COMMIT();       // unconditional: keeps wait_group accounting aligned
    }

    // ---- epilogue: O / l -> split bf16 into [M, C] ----
    float inv0 = 1.f / l0r, inv1 = 1.f / l1r;
    int brow = (head >> 3) << 10;
    int ncol = (head & 7) << 6;
    int r0   = q0 + wid * 16 + (lane >> 2);
    size_t off0 = (size_t)(brow + r0) * C_ + ncol + (lane & 3) * 2;
    size_t off1 = off0 + (size_t)8 * C_;
#pragma unroll
    for (int f = 0; f < 8; f++) {
        uint32_t ph, pl;
        packsplit(oa[f][0] * inv0, oa[f][1] * inv0, ph, pl);
        *(uint32_t*)(attHi + off0 + f * 8) = ph;
        *(uint32_t*)(attLo + off0 + f * 8) = pl;
        packsplit(oa[f][2] * inv1, oa[f][3] * inv1, ph, pl);
        *(uint32_t*)(attHi + off1 + f * 8) = ph;
        *(uint32_t*)(attLo + off1 + f * 8) = pl;
    }
}

// ---------------------------------------------------------------------------
// Embedding + interleave + LayerNorm (unchanged)
// ---------------------------------------------------------------------------
__global__ __launch_bounds__(256) void embed_kernel(
    const float* __restrict__ states, const float* __restrict__ actions,
    const float* __restrict__ We_s, const float* __restrict__ be_s,
    const float* __restrict__ We_a, const float* __restrict__ be_a,
    const float* __restrict__ pe,
    const float* __restrict__ g, const float* __restrict__ bt,
    float* __restrict__ H, bf16* __restrict__ Hhi, bf16* __restrict__ Hlo)
{
    __shared__ float xs[SD_];
    __shared__ float rs[256], rq[256];

    int row = blockIdx.x;
    int b   = row >> 10;
    int s   = row & 1023;
    int t   = s >> 1;
    int act = s & 1;
    int tid = threadIdx.x;

    int K            = act ? AD_ : SD_;
    const float* x   = act ? (actions + ((size_t)b * T_ + t) * AD_)
                           : (states  + ((size_t)b * T_ + t) * SD_);
    const float* W   = act ? We_a : We_s;
    const float* bia = act ? be_a : be_s;

    if (tid < K) xs[tid] = x[tid];
    __syncthreads();

    float v[2];
    float sum = 0.f, sumsq = 0.f;
#pragma unroll
    for (int e = 0; e < 2; e++) {
        int c = tid + e * 256;
        float a = bia[c] + pe[t * C_ + c];
        const float* wr = W + (size_t)c * K;
        for (int k = 0; k < K; k++) a += xs[k] * wr[k];
        v[e] = a;
        sum += a; sumsq += a * a;
    }
    rs[tid] = sum; rq[tid] = sumsq;
    __syncthreads();
    for (int off = 128; off > 0; off >>= 1) {
        if (tid < off) { rs[tid] += rs[tid + off]; rq[tid] += rq[tid + off]; }
        __syncthreads();
    }
    float mean = rs[0] * (1.f / C_);
    float var  = rq[0] * (1.f / C_) - mean * mean;
    float rstd = rsqrtf(var + 1e-5f);

#pragma unroll
    for (int e = 0; e < 2; e++) {
        int c = tid + e * 256;
        float y = (v[e] - mean) * rstd * g[c] + bt[c];
        size_t o = (size_t)row * C_ + c;
        H[o] = y;
        bf16 h, l; split2(y, h, l);
        Hhi[o] = h; Hlo[o] = l;
    }
}

// ---------------------------------------------------------------------------
// LayerNorm — 128 threads/row, float4 + warp shuffles, 2 syncs
// ---------------------------------------------------------------------------
__global__ __launch_bounds__(128) void ln_kernel(
    const float* __restrict__ in, float* __restrict__ out,
    bf16* __restrict__ outHi, bf16* __restrict__ outLo,
    const float* __restrict__ g, const float* __restrict__ bt)
{
    __shared__ float ws[4], wq[4];
    int row  = blockIdx.x;
    int tid  = threadIdx.x;
    int lane = tid & 31;
    int wd   = tid >> 5;

    float4 v = ((const float4*)(in + (size_t)row * C_))[tid];
    float sum = v.x + v.y + v.z + v.w;
    float sq  = v.x * v.x + v.y * v.y + v.z * v.z + v.w * v.w;
#pragma unroll
    for (int off = 16; off > 0; off >>= 1) {
        sum += __shfl_xor_sync(0xffffffffu, sum, off);
        sq  += __shfl_xor_sync(0xffffffffu, sq,  off);
    }
    if (lane == 0) { ws[wd] = sum; wq[wd] = sq; }
    __syncthreads();
    sum = ws[0] + ws[1] + ws[2] + ws[3];
    sq  = wq[0] + wq[1] + wq[2] + wq[3];

    float mean = sum * (1.f / C_);
    float var  = sq * (1.f / C_) - mean * mean;
    float rstd = rsqrtf(var + 1e-5f);

    float4 gv = ((const float4*)g)[tid];
    float4 bv = ((const float4*)bt)[tid];
    float4 y;
    y.x = (v.x - mean) * rstd * gv.x + bv.x;
    y.y = (v.y - mean) * rstd * gv.y + bv.y;
    y.z = (v.z - mean) * rstd * gv.z + bv.z;
    y.w = (v.w - mean) * rstd * gv.w + bv.w;

    ((float4*)(out + (size_t)row * C_))[tid] = y;
    uint32_t h01, l01, h23, l23;
    packsplit(y.x, y.y, h01, l01);
    packsplit(y.z, y.w, h23, l23);
    ((uint2*)(outHi + (size_t)row * C_))[tid] = make_uint2(h01, h23);
    ((uint2*)(outLo + (size_t)row * C_))[tid] = make_uint2(l01, l23);
}

// ---------------------------------------------------------------------------
// Output heads — 4 threads per output, quad shuffle reduce
// ---------------------------------------------------------------------------
__global__ __launch_bounds__(256) void heads_kernel(
    const float* __restrict__ H,
    const float* __restrict__ Wps, const float* __restrict__ bps,
    const float* __restrict__ Wpa, const float* __restrict__ bpa,
    float* __restrict__ out)
{
    __shared__ float rows[2 * C_];
    int bt  = blockIdx.x;
    int b   = bt >> 9;
    int t   = bt & 511;
    int tid = threadIdx.x;

    size_t base = ((size_t)(b << 10) + (t << 1)) * C_;
    ((float4*)rows)[tid] = ((const float4*)(H + base))[tid];
    __syncthreads();

    int o   = tid >> 2;     // 0..63
    int sub = tid & 3;
    if (o < SD_ + AD_) {
        const float* w;
        const float* r;
        if (o < SD_) { w = Wps + (size_t)o * C_;          r = rows + C_; }
        else         { w = Wpa + (size_t)(o - SD_) * C_;  r = rows; }
        float a = 0.f;
        int k0 = sub * 128;
#pragma unroll 4
        for (int k = 0; k < 128; k++) a += r[k0 + k] * w[k0 + k];
        a += __shfl_xor_sync(0xffffffffu, a, 1);
        a += __shfl_xor_sync(0xffffffffu, a, 2);
        if (sub == 0) {
            if (o < SD_) out[(size_t)bt * SD_ + o] = a + bps[o];
            else out[(size_t)(B_ * T_ * SD_) + (size_t)bt * AD_ + (o - SD_)] = a + bpa[o - SD_];
        }
    }
}

// ---------------------------------------------------------------------------
// Launch
// ---------------------------------------------------------------------------
extern "C" void kernel_launch(void* const* d_in, const int* in_sizes, int n_in,
                              void* d_out, int out_size)
{
    const float* states  = (const float*)d_in[0];
    const float* actions = (const float*)d_in[1];
    const float* We_s    = (const float*)d_in[2];
    const float* be_s    = (const float*)d_in[3];
    const float* We_a    = (const float*)d_in[4];
    const float* be_a    = (const float*)d_in[5];
    const float* pe      = (const float*)d_in[6];
    const float* g_emb   = (const float*)d_in[7];
    const float* b_emb   = (const float*)d_in[8];
    const float* Wq      = (const float*)d_in[9];
    const float* bq      = (const float*)d_in[10];
    const float* Wk      = (const float*)d_in[11];
    const float* bk      = (const float*)d_in[12];
    const float* Wv      = (const float*)d_in[13];
    const float* bv      = (const float*)d_in[14];
    const float* Wo      = (const float*)d_in[15];
    const float* bo      = (const float*)d_in[16];
    const float* W1      = (const float*)d_in[17];
    const float* b1      = (const float*)d_in[18];
    const float* W2      = (const float*)d_in[19];
    const float* b2      = (const float*)d_in[20];
    const float* g1      = (const float*)d_in[21];
    const float* bt1     = (const float*)d_in[22];
    const float* g2      = (const float*)d_in[23];
    const float* bt2     = (const float*)d_in[24];
    const float* Wps     = (const float*)d_in[25];
    const float* bps     = (const float*)d_in[26];
    const float* Wpa     = (const float*)d_in[27];
    const float* bpa     = (const float*)d_in[28];

    float *H, *tmp;
    bf16 *Hhi, *Hlo, *ATThi, *ATTlo, *FFhi, *FFlo, *Whi, *Wlo;
    bf16 *qhi, *qlo, *khi, *klo, *vhi, *vlo;
    cudaGetSymbolAddress((void**)&H,    g_H);
    cudaGetSymbolAddress((void**)&tmp,  g_tmp);
    cudaGetSymbolAddress((void**)&Hhi,  g_Hhi);
    cudaGetSymbolAddress((void**)&Hlo,  g_Hlo);
    cudaGetSymbolAddress((void**)&ATThi, g_ATThi);
    cudaGetSymbolAddress((void**)&ATTlo, g_ATTlo);
    cudaGetSymbolAddress((void**)&FFhi, g_FFhi);
    cudaGetSymbolAddress((void**)&FFlo, g_FFlo);
    cudaGetSymbolAddress((void**)&Whi,  g_Whi);
    cudaGetSymbolAddress((void**)&Wlo,  g_Wlo);
    cudaGetSymbolAddress((void**)&qhi,  g_qhi);
    cudaGetSymbolAddress((void**)&qlo,  g_qlo);
    cudaGetSymbolAddress((void**)&khi,  g_khi);
    cudaGetSymbolAddress((void**)&klo,  g_klo);
    cudaGetSymbolAddress((void**)&vhi,  g_vhi);
    cudaGetSymbolAddress((void**)&vlo,  g_vlo);

    cudaFuncSetAttribute(tc_gemm_kernel, cudaFuncAttributeMaxDynamicSharedMemorySize, DSMEM_SZ);
    cudaFuncSetAttribute(tc_qkv_kernel,  cudaFuncAttributeMaxDynamicSharedMemorySize, DSMEM_SZ);
    cudaFuncSetAttribute(attn_tc_kernel, cudaFuncAttributeMaxDynamicSharedMemorySize, ATT_SMEM);

    convert6_kernel<<<4096, 256>>>(Wq, Wk, Wv, Wo, W1, W2, Whi, Wlo);

    embed_kernel<<<MROWS, 256>>>(states, actions, We_s, be_s, We_a, be_a,
                                 pe, g_emb, b_emb, H, Hhi, Hlo);

    dim3 gC(C_ / 128, MROWS / 128);
    dim3 gF(FF_ / 128, MROWS / 128);
    dim3 gQKV(12, MROWS / 128);

    for (int i = 0; i < L_; i++) {
        size_t wC = (size_t)i * C_ * C_;
        size_t wF = (size_t)i * FF_ * C_;

        tc_qkv_kernel<<<gQKV, 256, DSMEM_SZ>>>(
            Hhi, Hlo,
            Whi + OW_Q + wC, Wlo + OW_Q + wC, bq + i * C_,
            Whi + OW_K + wC, Wlo + OW_K + wC, bk + i * C_,
            Whi + OW_V + wC, Wlo + OW_V + wC, bv + i * C_,
            qhi, qlo, khi, klo, vhi, vlo);

        attn_tc_kernel<<<dim3(S_ / 128, B_ * NH_), 256, ATT_SMEM>>>(
            qhi, qlo, khi, klo, vhi, vlo, ATThi, ATTlo);

        tc_gemm_kernel<<<gC, 256, DSMEM_SZ>>>(
            ATThi, ATTlo, Whi + OW_O + wC, Wlo + OW_O + wC,
            bo + i * C_, H, tmp, nullptr, nullptr, C_, C_, 0, 0);
        ln_kernel<<<MROWS, 128>>>(tmp, H, Hhi, Hlo, g1 + i * C_, bt1 + i * C_);

        tc_gemm_kernel<<<gF, 256, DSMEM_SZ>>>(
            Hhi, Hlo, Whi + OW_1 + wF, Wlo + OW_1 + wF,
            b1 + i * FF_, nullptr, nullptr, FFhi, FFlo, FF_, C_, 1, 0);

        tc_gemm_kernel<<<gC, 256, DSMEM_SZ>>>(
            FFhi, FFlo, Whi + OW_2 + wF, Wlo + OW_2 + wF,
            b2 + i * C_, H, tmp, nullptr, nullptr, C_, FF_, 0, 0);
        ln_kernel<<<MROWS, 128>>>(tmp, H, Hhi, Hlo, g2 + i * C_, bt2 + i * C_);
    }

    heads_kernel<<<B_ * T_, 256>>>(H, Wps, bps, Wpa, bpa, (float*)d_out);
}

// round 11
// speedup vs baseline: 1.0119x; 1.0119x over previous
#include <cuda_runtime.h>
#include <cuda_bf16.h>
#include <math.h>
#include <stdint.h>

// Problem constants
#define B_     8
#define T_     512
#define C_     512
#define L_     4
#define NH_    8
#define DH_    64
#define S_     1024
#define MROWS  8192
#define FF_    2048
#define SD_    48
#define AD_    12

typedef __nv_bfloat16 bf16;

// ---------------------------------------------------------------------------
// Static scratch
// ---------------------------------------------------------------------------
__device__ float g_H  [MROWS * C_];
__device__ float g_tmp[MROWS * C_];

__device__ bf16 g_Hhi [MROWS * C_],  g_Hlo [MROWS * C_];
__device__ bf16 g_ATThi[MROWS * C_], g_ATTlo[MROWS * C_];
__device__ bf16 g_FFhi[MROWS * FF_], g_FFlo[MROWS * FF_];

__device__ bf16 g_qhi[MROWS * C_], g_qlo[MROWS * C_];
__device__ bf16 g_khi[MROWS * C_], g_klo[MROWS * C_];
__device__ bf16 g_vhi[MROWS * C_], g_vlo[MROWS * C_];

#define OW_Q 0
#define OW_K (L_ * C_ * C_)
#define OW_V (2 * L_ * C_ * C_)
#define OW_O (3 * L_ * C_ * C_)
#define OW_1 (4 * L_ * C_ * C_)
#define OW_2 (4 * L_ * C_ * C_ + L_ * FF_ * C_)
#define WTOT (4 * L_ * C_ * C_ + 2 * L_ * FF_ * C_)
__device__ bf16 g_Whi[WTOT], g_Wlo[WTOT];

// ---------------------------------------------------------------------------
// PTX helpers (sm_80-era, valid on plain sm_100 target)
// ---------------------------------------------------------------------------
__device__ __forceinline__ uint32_t smem_u32(const void* p) {
    uint32_t a;
    asm("{ .reg .u64 t; cvta.to.shared.u64 t, %1; cvt.u32.u64 %0, t; }"
        : "=r"(a) : "l"(p));
    return a;
}

#define CP16(dst, src) \
    asm volatile("cp.async.cg.shared.global [%0], [%1], 16;" \
                 :: "r"(dst), "l"(src) : "memory")
#define CP_COMMIT()  asm volatile("cp.async.commit_group;" ::: "memory")
#define CP_WAIT1()   asm volatile("cp.async.wait_group 1;" ::: "memory")
#define CP_WAIT0()   asm volatile("cp.async.wait_group 0;" ::: "memory")

#define LDM_X4(r0, r1, r2, r3, addr) \
    asm volatile("ldmatrix.sync.aligned.m8n8.x4.shared.b16 {%0,%1,%2,%3}, [%4];" \
                 : "=r"(r0), "=r"(r1), "=r"(r2), "=r"(r3) : "r"(addr))

#define LDM_X4_T(r0, r1, r2, r3, addr) \
    asm volatile("ldmatrix.sync.aligned.m8n8.x4.trans.shared.b16 {%0,%1,%2,%3}, [%4];" \
                 : "=r"(r0), "=r"(r1), "=r"(r2), "=r"(r3) : "r"(addr))

#define MMA_BF16(c, a, b) \
    asm volatile("mma.sync.aligned.m16n8k16.row.col.f32.bf16.bf16.f32 " \
                 "{%0,%1,%2,%3}, {%4,%5,%6,%7}, {%8,%9}, {%0,%1,%2,%3};" \
                 : "+f"((c)[0]), "+f"((c)[1]), "+f"((c)[2]), "+f"((c)[3]) \
                 : "r"((a)[0]), "r"((a)[1]), "r"((a)[2]), "r"((a)[3]), \
                   "r"((b)[0]), "r"((b)[1]))

__device__ __forceinline__ void split2(float v, bf16& h, bf16& l) {
    h = __float2bfloat16(v);
    l = __float2bfloat16(v - __bfloat162float(h));
}

__device__ __forceinline__ void packsplit(float a, float b, uint32_t& ph, uint32_t& pl) {
    __nv_bfloat162 h2, l2;
    bf16 ha, la, hb, lb;
    split2(a, ha, la); split2(b, hb, lb);
    h2.x = ha; h2.y = hb; l2.x = la; l2.y = lb;
    ph = *(uint32_t*)&h2; pl = *(uint32_t*)&l2;
}

// ---------------------------------------------------------------------------
// Merged fp32 -> (hi, lo) bf16 converter for all six weight groups
// ---------------------------------------------------------------------------
#define CS_Q (L_ * C_ * C_ / 4)
#define CS_W1 (L_ * FF_ * C_ / 4)
#define CTOT4 (4 * CS_Q + 2 * CS_W1)

__global__ __launch_bounds__(256) void convert6_kernel(
    const float* __restrict__ Wq, const float* __restrict__ Wk,
    const float* __restrict__ Wv, const float* __restrict__ Wo,
    const float* __restrict__ W1, const float* __restrict__ W2,
    bf16* __restrict__ hi, bf16* __restrict__ lo)
{
    for (int i = blockIdx.x * 256 + threadIdx.x; i < CTOT4; i += gridDim.x * 256) {
        const float* src;
        int li;
        if      (i < CS_Q)      { src = Wq; li = i; }
        else if (i < 2 * CS_Q)  { src = Wk; li = i - CS_Q; }
        else if (i < 3 * CS_Q)  { src = Wv; li = i - 2 * CS_Q; }
        else if (i < 4 * CS_Q)  { src = Wo; li = i - 3 * CS_Q; }
        else if (i < 4 * CS_Q + CS_W1) { src = W1; li = i - 4 * CS_Q; }
        else                    { src = W2; li = i - 4 * CS_Q - CS_W1; }
        float4 v = ((const float4*)src)[li];
        uint32_t h01, l01, h23, l23;
        packsplit(v.x, v.y, h01, l01);
        packsplit(v.z, v.w, h23, l23);
        ((uint2*)hi)[i] = make_uint2(h01, h23);
        ((uint2*)lo)[i] = make_uint2(l01, l23);
    }
}

// ---------------------------------------------------------------------------
// Tensor-core GEMM via mma.sync, split-bf16 (hh + hl + lh), 2 CTAs/SM.
// Warp tile 64x32 (2x4 warp grid): MMA:LDSM ratio ~4.8:1.
// ---------------------------------------------------------------------------
#define RS_B    80
#define TILE_B  (128 * RS_B)
#define STAGE_B (4 * TILE_B)
#define DSMEM_SZ (2 * STAGE_B)

__device__ __forceinline__ void issue_stage(
    const bf16* __restrict__ Ahi, const bf16* __restrict__ Alo,
    const bf16* __restrict__ Bhi, const bf16* __restrict__ Blo,
    int m0, int n0, int K, int k0, uint32_t sstage, int tid)
{
#pragma unroll
    for (int it = 0; it < 8; it++) {
        int id  = tid + it * 256;
        int mat = id >> 9;
        int rem = id & 511;
        int r   = rem >> 2;
        int c   = rem & 3;
        const bf16* src = (mat == 0) ? Ahi : (mat == 1) ? Alo : (mat == 2) ? Bhi : Blo;
        int rowbase = (mat < 2) ? m0 : n0;
        const bf16* gp = src + (size_t)(rowbase + r) * K + k0 + c * 8;
        uint32_t dst = sstage + mat * TILE_B + r * RS_B + c * 16;
        CP16(dst, gp);
    }
    CP_COMMIT();
}

__device__ __forceinline__ void tc_gemm_body(
    const bf16* __restrict__ Ahi, const bf16* __restrict__ Alo,
    const bf16* __restrict__ Bhi, const bf16* __restrict__ Blo,
    const float* __restrict__ bias, const float* __restrict__ resid,
    float* __restrict__ outF, bf16* __restrict__ outHi, bf16* __restrict__ outLo,
    int Nn, int K, int gelu, int headLayout, float oscale, int bx, int by)
{
    extern __shared__ char dsm[];
    uint32_t sbase = smem_u32(dsm);

    int tid  = threadIdx.x;
    int lane = tid & 31;
    int wid  = tid >> 5;
    int wm0  = (wid & 1) * 64;     // 2 warps in m
    int wn0  = (wid >> 1) * 32;    // 4 warps in n
    int m0   = by * 128;
    int n0   = bx * 128;

    float acc[4][4][4];            // mt, nf(n8), e
#pragma unroll
    for (int mt = 0; mt < 4; mt++)
#pragma unroll
        for (int nf = 0; nf < 4; nf++)
#pragma unroll
            for (int e = 0; e < 4; e++) acc[mt][nf][e] = 0.f;

    int S = K >> 5;

    issue_stage(Ahi, Alo, Bhi, Blo, m0, n0, K, 0, sbase, tid);

    int aRow = wm0 + (lane & 15);
    int aColB = ((lane >> 4) * 8) * 2;
    int bRowOff = (lane & 7) + ((lane >> 4) << 3);
    int bColB = (((lane >> 3) & 1) * 8) * 2;

    for (int s = 0; s < S; s++) {
        if (s + 1 < S) {
            issue_stage(Ahi, Alo, Bhi, Blo, m0, n0, K, (s + 1) << 5,
                        sbase + ((s + 1) & 1) * STAGE_B, tid);
            CP_WAIT1();
        } else {
            CP_WAIT0();
        }
        __syncthreads();

        uint32_t st  = sbase + (s & 1) * STAGE_B;
        uint32_t sAh = st;
        uint32_t sAl = st + TILE_B;
        uint32_t sBh = st + 2 * TILE_B;
        uint32_t sBl = st + 3 * TILE_B;

#pragma unroll
        for (int kk = 0; kk < 2; kk++) {
            uint32_t kByte = kk * 32;

            uint32_t ah[4][4], al[4][4];
#pragma unroll
            for (int mt = 0; mt < 4; mt++) {
                uint32_t addr = sAh + (aRow + mt * 16) * RS_B + kByte + aColB;
                LDM_X4(ah[mt][0], ah[mt][1], ah[mt][2], ah[mt][3], addr);
                addr = sAl + (aRow + mt * 16) * RS_B + kByte + aColB;
                LDM_X4(al[mt][0], al[mt][1], al[mt][2], al[mt][3], addr);
            }

#pragma unroll
            for (int nt = 0; nt < 2; nt++) {
                uint32_t bh0[2], bh1[2], bl0[2], bl1[2];
                uint32_t addr = sBh + (wn0 + nt * 16 + bRowOff) * RS_B + kByte + bColB;
                LDM_X4(bh0[0], bh0[1], bh1[0], bh1[1], addr);
                addr = sBl + (wn0 + nt * 16 + bRowOff) * RS_B + kByte + bColB;
                LDM_X4(bl0[0], bl0[1], bl1[0], bl1[1], addr);
#pragma unroll
                for (int mt = 0; mt < 4; mt++) {
                    MMA_BF16(acc[mt][2 * nt],     ah[mt], bh0);
                    MMA_BF16(acc[mt][2 * nt],     ah[mt], bl0);
                    MMA_BF16(acc[mt][2 * nt],     al[mt], bh0);
                    MMA_BF16(acc[mt][2 * nt + 1], ah[mt], bh1);
                    MMA_BF16(acc[mt][2 * nt + 1], ah[mt], bl1);
                    MMA_BF16(acc[mt][2 * nt + 1], al[mt], bh1);
                }
            }
        }
        __syncthreads();
    }

    // epilogue
#pragma unroll
    for (int mt = 0; mt < 4; mt++) {
#pragma unroll
        for (int rr = 0; rr < 2; rr++) {
            int m = m0 + wm0 + mt * 16 + (lane >> 2) + rr * 8;
#pragma unroll
            for (int nf = 0; nf < 4; nf++) {
                int c0 = n0 + wn0 + nf * 8 + (lane & 3) * 2;
                float v0 = (acc[mt][nf][rr * 2 + 0] + bias[c0]) * oscale;
                float v1 = (acc[mt][nf][rr * 2 + 1] + bias[c0 + 1]) * oscale;
                if (resid) {
                    const float2 rv = *(const float2*)(resid + (size_t)m * Nn + c0);
                    v0 += rv.x; v1 += rv.y;
                }
                if (gelu) {
                    v0 = 0.5f * v0 * (1.f + erff(v0 * 0.70710678118654752f));
                    v1 = 0.5f * v1 * (1.f + erff(v1 * 0.70710678118654752f));
                }
                if (outF) {
                    float* dst;
                    if (headLayout) {
                        int bb = m >> 10, sR = m & 1023, hd = c0 >> 6, d0 = c0 & 63;
                        dst = outF + (((size_t)(bb * NH_ + hd) * S_) + sR) * DH_ + d0;
                    } else {
                        dst = outF + (size_t)m * Nn + c0;
                    }
                    *(float2*)dst = make_float2(v0, v1);
                } else {
                    size_t off;
                    if (headLayout) {
                        int bb = m >> 10, sR = m & 1023, hd = c0 >> 6, d0 = c0 & 63;
                        off = (((size_t)(bb * NH_ + hd) * S_) + sR) * DH_ + d0;
                    } else {
                        off = (size_t)m * Nn + c0;
                    }
                    uint32_t ph, pl;
                    packsplit(v0, v1, ph, pl);
                    *(uint32_t*)(outHi + off) = ph;
                    *(uint32_t*)(outLo + off) = pl;
                }
            }
        }
    }
}

__global__ __launch_bounds__(256, 2) void tc_gemm_kernel(
    const bf16* Ahi, const bf16* Alo, const bf16* Bhi, const bf16* Blo,
    const float* bias, const float* resid,
    float* outF, bf16* outHi, bf16* outLo,
    int Nn, int K, int gelu, int headLayout)
{
    tc_gemm_body(Ahi, Alo, Bhi, Blo, bias, resid, outF, outHi, outLo,
                 Nn, K, gelu, headLayout, 1.0f, blockIdx.x, blockIdx.y);
}

// Fused Q/K/V: grid.x = 12; outputs split bf16 head-layout; Q scaled by 0.125.
__global__ __launch_bounds__(256, 2) void tc_qkv_kernel(
    const bf16* Ahi, const bf16* Alo,
    const bf16* Wqh, const bf16* Wql, const float* bq,
    const bf16* Wkh, const bf16* Wkl, const float* bk,
    const bf16* Wvh, const bf16* Wvl, const float* bv,
    bf16* qhi, bf16* qlo, bf16* khi, bf16* klo, bf16* vhi, bf16* vlo)
{
    int which = blockIdx.x >> 2;
    int bx    = blockIdx.x & 3;
    const bf16* Bh  = (which == 0) ? Wqh : (which == 1) ? Wkh : Wvh;
    const bf16* Bl  = (which == 0) ? Wql : (which == 1) ? Wkl : Wvl;
    const float* bi = (which == 0) ? bq  : (which == 1) ? bk  : bv;
    bf16* oh        = (which == 0) ? qhi : (which == 1) ? khi : vhi;
    bf16* ol        = (which == 0) ? qlo : (which == 1) ? klo : vlo;
    float sc        = (which == 0) ? 0.125f : 1.0f;
    tc_gemm_body(Ahi, Alo, Bh, Bl, bi, nullptr, nullptr, oh, ol,
                 C_, C_, 0, 1, sc, bx, blockIdx.y);
}

// ---------------------------------------------------------------------------
// Tensor-core causal flash attention (R9 version: 64x64 tiles, 128 threads).
// ---------------------------------------------------------------------------
#define RSA_B  144
#define AT_QH  0
#define AT_QL  (64 * RSA_B)
#define AT_KH  (2 * 64 * RSA_B)
#define AT_KL  (3 * 64 * RSA_B)
#define AT_VH  (4 * 64 * RSA_B)
#define AT_VL  (5 * 64 * RSA_B)
#define ATT_SMEM (6 * 64 * RSA_B)

__global__ __launch_bounds__(128) void attn_tc_kernel(
    const bf16* __restrict__ Qhi, const bf16* __restrict__ Qlo,
    const bf16* __restrict__ Khi, const bf16* __restrict__ Klo,
    const bf16* __restrict__ Vhi, const bf16* __restrict__ Vlo,
    bf16* __restrict__ attHi, bf16* __restrict__ attLo)
{
    extern __shared__ char sm[];
    uint32_t sb = smem_u32(sm);

    int tid  = threadIdx.x;
    int lane = tid & 31;
    int wid  = tid >> 5;
    int head = blockIdx.y;
    int q0   = blockIdx.x * 64;
    size_t base = (size_t)head * S_ * DH_;

    {
        int r = tid >> 1, hf = tid & 1;
        const uint4* gh = (const uint4*)(Qhi + base + (size_t)(q0 + r) * DH_ + hf * 32);
        const uint4* gl = (const uint4*)(Qlo + base + (size_t)(q0 + r) * DH_ + hf * 32);
        uint4* shq = (uint4*)(sm + AT_QH + r * RSA_B + hf * 64);
        uint4* slq = (uint4*)(sm + AT_QL + r * RSA_B + hf * 64);
#pragma unroll
        for (int e = 0; e < 4; e++) { shq[e] = gh[e]; slq[e] = gl[e]; }
    }
    __syncthreads();

    int aRow = (lane & 15);
    int aCol = (lane >> 4) * 16;
    uint32_t qh[4][4], ql[4][4];
#pragma unroll
    for (int kc = 0; kc < 4; kc++) {
        uint32_t addr = sb + AT_QH + (wid * 16 + aRow) * RSA_B + kc * 32 + aCol;
        LDM_X4(qh[kc][0], qh[kc][1], qh[kc][2], qh[kc][3], addr);
        addr = sb + AT_QL + (wid * 16 + aRow) * RSA_B + kc * 32 + aCol;
        LDM_X4(ql[kc][0], ql[kc][1], ql[kc][2], ql[kc][3], addr);
    }

    int bRow = (lane & 7) + ((lane >> 4) << 3);
    int bCol = ((lane >> 3) & 1) * 16;
    int vRow = (lane & 7) + (((lane >> 3) & 1) << 3);
    int vCol = (lane >> 4) * 16;

    float oa[8][4];
#pragma unroll
    for (int f = 0; f < 8; f++)
#pragma unroll
        for (int e = 0; e < 4; e++) oa[f][e] = 0.f;
    float m0r = -1e30f, m1r = -1e30f, l0r = 0.f, l1r = 0.f;

    int nTiles = blockIdx.x + 1;
    for (int kt = 0; kt < nTiles; kt++) {
        int k0 = kt * 64;
        __syncthreads();
        {
            int r = tid >> 1, hf = tid & 1;
            size_t goff = base + (size_t)(k0 + r) * DH_ + hf * 32;
            const uint4* gkh = (const uint4*)(Khi + goff);
            const uint4* gkl = (const uint4*)(Klo + goff);
            const uint4* gvh = (const uint4*)(Vhi + goff);
            const uint4* gvl = (const uint4*)(Vlo + goff);
            uint32_t so = r * RSA_B + hf * 64;
            uint4* skh = (uint4*)(sm + AT_KH + so);
            uint4* skl = (uint4*)(sm + AT_KL + so);
            uint4* svh = (uint4*)(sm + AT_VH + so);
            uint4* svl = (uint4*)(sm + AT_VL + so);
#pragma unroll
            for (int e = 0; e < 4; e++) {
                skh[e] = gkh[e]; skl[e] = gkl[e];
                svh[e] = gvh[e]; svl[e] = gvl[e];
            }
        }
        __syncthreads();

        float sc[8][4];
#pragma unroll
        for (int f = 0; f < 8; f++)
#pragma unroll
            for (int e = 0; e < 4; e++) sc[f][e] = 0.f;

#pragma unroll
        for (int kc = 0; kc < 4; kc++) {
#pragma unroll
            for (int ntk = 0; ntk < 4; ntk++) {
                uint32_t h0, h1, h2, h3, g0, g1, g2, g3;
                uint32_t addr = sb + AT_KH + (ntk * 16 + bRow) * RSA_B + kc * 32 + bCol;
                LDM_X4(h0, h1, h2, h3, addr);
                addr = sb + AT_KL + (ntk * 16 + bRow) * RSA_B + kc * 32 + bCol;
                LDM_X4(g0, g1, g2, g3, addr);
                uint32_t bh0[2] = {h0, h1}, bh1[2] = {h2, h3};
                uint32_t bl0[2] = {g0, g1}, bl1[2] = {g2, g3};
                MMA_BF16(sc[2 * ntk],     qh[kc], bh0);
                MMA_BF16(sc[2 * ntk],     qh[kc], bl0);
                MMA_BF16(sc[2 * ntk],     ql[kc], bh0);
                MMA_BF16(sc[2 * ntk + 1], qh[kc], bh1);
                MMA_BF16(sc[2 * ntk + 1], qh[kc], bl1);
                MMA_BF16(sc[2 * ntk + 1], ql[kc], bh1);
            }
        }

        if (kt == nTiles - 1) {
            int rg = q0 + wid * 16 + (lane >> 2);
#pragma unroll
            for (int f = 0; f < 8; f++) {
                int c = k0 + f * 8 + (lane & 3) * 2;
                if (c     > rg)     sc[f][0] = -1e30f;
                if (c + 1 > rg)     sc[f][1] = -1e30f;
                if (c     > rg + 8) sc[f][2] = -1e30f;
                if (c + 1 > rg + 8) sc[f][3] = -1e30f;
            }
        }

        float mx0 = -1e30f, mx1 = -1e30f;
#pragma unroll
        for (int f = 0; f < 8; f++) {
            mx0 = fmaxf(mx0, fmaxf(sc[f][0], sc[f][1]));
            mx1 = fmaxf(mx1, fmaxf(sc[f][2], sc[f][3]));
        }
        mx0 = fmaxf(mx0, __shfl_xor_sync(0xffffffffu, mx0, 1));
        mx0 = fmaxf(mx0, __shfl_xor_sync(0xffffffffu, mx0, 2));
        mx1 = fmaxf(mx1, __shfl_xor_sync(0xffffffffu, mx1, 1));
        mx1 = fmaxf(mx1, __shfl_xor_sync(0xffffffffu, mx1, 2));
        float mn0 = fmaxf(m0r, mx0);
        float mn1 = fmaxf(m1r, mx1);

        float sum0 = 0.f, sum1 = 0.f;
#pragma unroll
        for (int f = 0; f < 8; f++) {
            sc[f][0] = __expf(sc[f][0] - mn0);
            sc[f][1] = __expf(sc[f][1] - mn0);
            sc[f][2] = __expf(sc[f][2] - mn1);
            sc[f][3] = __expf(sc[f][3] - mn1);
            sum0 += sc[f][0] + sc[f][1];
            sum1 += sc[f][2] + sc[f][3];
        }
        sum0 += __shfl_xor_sync(0xffffffffu, sum0, 1);
        sum0 += __shfl_xor_sync(0xffffffffu, sum0, 2);
        sum1 += __shfl_xor_sync(0xffffffffu, sum1, 1);
        sum1 += __shfl_xor_sync(0xffffffffu, sum1, 2);

        float cr0 = __expf(m0r - mn0);
        float cr1 = __expf(m1r - mn1);
        l0r = l0r * cr0 + sum0;
        l1r = l1r * cr1 + sum1;
        m0r = mn0; m1r = mn1;
#pragma unroll
        for (int f = 0; f < 8; f++) {
            oa[f][0] *= cr0; oa[f][1] *= cr0;
            oa[f][2] *= cr1; oa[f][3] *= cr1;
        }

#pragma unroll
        for (int kc = 0; kc < 4; kc++) {
            uint32_t ph[4], pl[4];
            packsplit(sc[2 * kc][0],     sc[2 * kc][1],     ph[0], pl[0]);
            packsplit(sc[2 * kc][2],     sc[2 * kc][3],     ph[1], pl[1]);
            packsplit(sc[2 * kc + 1][0], sc[2 * kc + 1][1], ph[2], pl[2]);
            packsplit(sc[2 * kc + 1][2], sc[2 * kc + 1][3], ph[3], pl[3]);
#pragma unroll
            for (int nt = 0; nt < 4; nt++) {
                uint32_t h0, h1, h2, h3, g0, g1, g2, g3;
                uint32_t addr = sb + AT_VH + (kc * 16 + vRow) * RSA_B + nt * 32 + vCol;
                LDM_X4_T(h0, h1, h2, h3, addr);
                addr = sb + AT_VL + (kc * 16 + vRow) * RSA_B + nt * 32 + vCol;
                LDM_X4_T(g0, g1, g2, g3, addr);
                uint32_t vh0[2] = {h0, h1}, vh1[2] = {h2, h3};
                uint32_t vl0[2] = {g0, g1}, vl1[2] = {g2, g3};
                MMA_BF16(oa[2 * nt],     ph, vh0);
                MMA_BF16(oa[2 * nt],     ph, vl0);
                MMA_BF16(oa[2 * nt],     pl, vh0);
                MMA_BF16(oa[2 * nt + 1], ph, vh1);
                MMA_BF16(oa[2 * nt + 1], ph, vl1);
                MMA_BF16(oa[2 * nt + 1], pl, vh1);
            }
        }
    }

    float inv0 = 1.f / l0r, inv1 = 1.f / l1r;
    int brow = (head >> 3) << 10;
    int ncol = (head & 7) << 6;
    int r0   = q0 + wid * 16 + (lane >> 2);
    size_t off0 = (size_t)(brow + r0) * C_ + ncol + (lane & 3) * 2;
    size_t off1 = off0 + (size_t)8 * C_;
#pragma unroll
    for (int f = 0; f < 8; f++) {
        uint32_t ph, pl;
        packsplit(oa[f][0] * inv0, oa[f][1] * inv0, ph, pl);
        *(uint32_t*)(attHi + off0 + f * 8) = ph;
        *(uint32_t*)(attLo + off0 + f * 8) = pl;
        packsplit(oa[f][2] * inv1, oa[f][3] * inv1, ph, pl);
        *(uint32_t*)(attHi + off1 + f * 8) = ph;
        *(uint32_t*)(attLo + off1 + f * 8) = pl;
    }
}

// ---------------------------------------------------------------------------
// Embedding + interleave + LayerNorm (unchanged)
// ---------------------------------------------------------------------------
__global__ __launch_bounds__(256) void embed_kernel(
    const float* __restrict__ states, const float* __restrict__ actions,
    const float* __restrict__ We_s, const float* __restrict__ be_s,
    const float* __restrict__ We_a, const float* __restrict__ be_a,
    const float* __restrict__ pe,
    const float* __restrict__ g, const float* __restrict__ bt,
    float* __restrict__ H, bf16* __restrict__ Hhi, bf16* __restrict__ Hlo)
{
    __shared__ float xs[SD_];
    __shared__ float rs[256], rq[256];

    int row = blockIdx.x;
    int b   = row >> 10;
    int s   = row & 1023;
    int t   = s >> 1;
    int act = s & 1;
    int tid = threadIdx.x;

    int K            = act ? AD_ : SD_;
    const float* x   = act ? (actions + ((size_t)b * T_ + t) * AD_)
                           : (states  + ((size_t)b * T_ + t) * SD_);
    const float* W   = act ? We_a : We_s;
    const float* bia = act ? be_a : be_s;

    if (tid < K) xs[tid] = x[tid];
    __syncthreads();

    float v[2];
    float sum = 0.f, sumsq = 0.f;
#pragma unroll
    for (int e = 0; e < 2; e++) {
        int c = tid + e * 256;
        float a = bia[c] + pe[t * C_ + c];
        const float* wr = W + (size_t)c * K;
        for (int k = 0; k < K; k++) a += xs[k] * wr[k];
        v[e] = a;
        sum += a; sumsq += a * a;
    }
    rs[tid] = sum; rq[tid] = sumsq;
    __syncthreads();
    for (int off = 128; off > 0; off >>= 1) {
        if (tid < off) { rs[tid] += rs[tid + off]; rq[tid] += rq[tid + off]; }
        __syncthreads();
    }
    float mean = rs[0] * (1.f / C_);
    float var  = rq[0] * (1.f / C_) - mean * mean;
    float rstd = rsqrtf(var + 1e-5f);

#pragma unroll
    for (int e = 0; e < 2; e++) {
        int c = tid + e * 256;
        float y = (v[e] - mean) * rstd * g[c] + bt[c];
        size_t o = (size_t)row * C_ + c;
        H[o] = y;
        bf16 h, l; split2(y, h, l);
        Hhi[o] = h; Hlo[o] = l;
    }
}

// ---------------------------------------------------------------------------
// LayerNorm — 128 threads/row, float4 + warp shuffles, 2 syncs
// ---------------------------------------------------------------------------
__global__ __launch_bounds__(128) void ln_kernel(
    const float* __restrict__ in, float* __restrict__ out,
    bf16* __restrict__ outHi, bf16* __restrict__ outLo,
    const float* __restrict__ g, const float* __restrict__ bt)
{
    __shared__ float ws[4], wq[4];
    int row  = blockIdx.x;
    int tid  = threadIdx.x;
    int lane = tid & 31;
    int wd   = tid >> 5;

    float4 v = ((const float4*)(in + (size_t)row * C_))[tid];
    float sum = v.x + v.y + v.z + v.w;
    float sq  = v.x * v.x + v.y * v.y + v.z * v.z + v.w * v.w;
#pragma unroll
    for (int off = 16; off > 0; off >>= 1) {
        sum += __shfl_xor_sync(0xffffffffu, sum, off);
        sq  += __shfl_xor_sync(0xffffffffu, sq,  off);
    }
    if (lane == 0) { ws[wd] = sum; wq[wd] = sq; }
    __syncthreads();
    sum = ws[0] + ws[1] + ws[2] + ws[3];
    sq  = wq[0] + wq[1] + wq[2] + wq[3];

    float mean = sum * (1.f / C_);
    float var  = sq * (1.f / C_) - mean * mean;
    float rstd = rsqrtf(var + 1e-5f);

    float4 gv = ((const float4*)g)[tid];
    float4 bv = ((const float4*)bt)[tid];
    float4 y;
    y.x = (v.x - mean) * rstd * gv.x + bv.x;
    y.y = (v.y - mean) * rstd * gv.y + bv.y;
    y.z = (v.z - mean) * rstd * gv.z + bv.z;
    y.w = (v.w - mean) * rstd * gv.w + bv.w;

    ((float4*)(out + (size_t)row * C_))[tid] = y;
    uint32_t h01, l01, h23, l23;
    packsplit(y.x, y.y, h01, l01);
    packsplit(y.z, y.w, h23, l23);
    ((uint2*)(outHi + (size_t)row * C_))[tid] = make_uint2(h01, h23);
    ((uint2*)(outLo + (size_t)row * C_))[tid] = make_uint2(l01, l23);
}

// ---------------------------------------------------------------------------
// Output heads — 4 threads per output, quad shuffle reduce
// ---------------------------------------------------------------------------
__global__ __launch_bounds__(256) void heads_kernel(
    const float* __restrict__ H,
    const float* __restrict__ Wps, const float* __restrict__ bps,
    const float* __restrict__ Wpa, const float* __restrict__ bpa,
    float* __restrict__ out)
{
    __shared__ float rows[2 * C_];
    int bt  = blockIdx.x;
    int b   = bt >> 9;
    int t   = bt & 511;
    int tid = threadIdx.x;

    size_t base = ((size_t)(b << 10) + (t << 1)) * C_;
    ((float4*)rows)[tid] = ((const float4*)(H + base))[tid];
    __syncthreads();

    int o   = tid >> 2;     // 0..63
    int sub = tid & 3;
    if (o < SD_ + AD_) {
        const float* w;
        const float* r;
        if (o < SD_) { w = Wps + (size_t)o * C_;          r = rows + C_; }
        else         { w = Wpa + (size_t)(o - SD_) * C_;  r = rows; }
        float a = 0.f;
        int k0 = sub * 128;
#pragma unroll 4
        for (int k = 0; k < 128; k++) a += r[k0 + k] * w[k0 + k];
        a += __shfl_xor_sync(0xffffffffu, a, 1);
        a += __shfl_xor_sync(0xffffffffu, a, 2);
        if (sub == 0) {
            if (o < SD_) out[(size_t)bt * SD_ + o] = a + bps[o];
            else out[(size_t)(B_ * T_ * SD_) + (size_t)bt * AD_ + (o - SD_)] = a + bpa[o - SD_];
        }
    }
}

// ---------------------------------------------------------------------------
// Launch
// ---------------------------------------------------------------------------
extern "C" void kernel_launch(void* const* d_in, const int* in_sizes, int n_in,
                              void* d_out, int out_size)
{
    const float* states  = (const float*)d_in[0];
    const float* actions = (const float*)d_in[1];
    const float* We_s    = (const float*)d_in[2];
    const float* be_s    = (const float*)d_in[3];
    const float* We_a    = (const float*)d_in[4];
    const float* be_a    = (const float*)d_in[5];
    const float* pe      = (const float*)d_in[6];
    const float* g_emb   = (const float*)d_in[7];
    const float* b_emb   = (const float*)d_in[8];
    const float* Wq      = (const float*)d_in[9];
    const float* bq      = (const float*)d_in[10];
    const float* Wk      = (const float*)d_in[11];
    const float* bk      = (const float*)d_in[12];
    const float* Wv      = (const float*)d_in[13];
    const float* bv      = (const float*)d_in[14];
    const float* Wo      = (const float*)d_in[15];
    const float* bo      = (const float*)d_in[16];
    const float* W1      = (const float*)d_in[17];
    const float* b1      = (const float*)d_in[18];
    const float* W2      = (const float*)d_in[19];
    const float* b2      = (const float*)d_in[20];
    const float* g1      = (const float*)d_in[21];
    const float* bt1     = (const float*)d_in[22];
    const float* g2      = (const float*)d_in[23];
    const float* bt2     = (const float*)d_in[24];
    const float* Wps     = (const float*)d_in[25];
    const float* bps     = (const float*)d_in[26];
    const float* Wpa     = (const float*)d_in[27];
    const float* bpa     = (const float*)d_in[28];

    float *H, *tmp;
    bf16 *Hhi, *Hlo, *ATThi, *ATTlo, *FFhi, *FFlo, *Whi, *Wlo;
    bf16 *qhi, *qlo, *khi, *klo, *vhi, *vlo;
    cudaGetSymbolAddress((void**)&H,    g_H);
    cudaGetSymbolAddress((void**)&tmp,  g_tmp);
    cudaGetSymbolAddress((void**)&Hhi,  g_Hhi);
    cudaGetSymbolAddress((void**)&Hlo,  g_Hlo);
    cudaGetSymbolAddress((void**)&ATThi, g_ATThi);
    cudaGetSymbolAddress((void**)&ATTlo, g_ATTlo);
    cudaGetSymbolAddress((void**)&FFhi, g_FFhi);
    cudaGetSymbolAddress((void**)&FFlo, g_FFlo);
    cudaGetSymbolAddress((void**)&Whi,  g_Whi);
    cudaGetSymbolAddress((void**)&Wlo,  g_Wlo);
    cudaGetSymbolAddress((void**)&qhi,  g_qhi);
    cudaGetSymbolAddress((void**)&qlo,  g_qlo);
    cudaGetSymbolAddress((void**)&khi,  g_khi);
    cudaGetSymbolAddress((void**)&klo,  g_klo);
    cudaGetSymbolAddress((void**)&vhi,  g_vhi);
    cudaGetSymbolAddress((void**)&vlo,  g_vlo);

    cudaFuncSetAttribute(tc_gemm_kernel, cudaFuncAttributeMaxDynamicSharedMemorySize, DSMEM_SZ);
    cudaFuncSetAttribute(tc_qkv_kernel,  cudaFuncAttributeMaxDynamicSharedMemorySize, DSMEM_SZ);
    cudaFuncSetAttribute(attn_tc_kernel, cudaFuncAttributeMaxDynamicSharedMemorySize, ATT_SMEM);

    convert6_kernel<<<4096, 256>>>(Wq, Wk, Wv, Wo, W1, W2, Whi, Wlo);

    embed_kernel<<<MROWS, 256>>>(states, actions, We_s, be_s, We_a, be_a,
                                 pe, g_emb, b_emb, H, Hhi, Hlo);

    dim3 gC(C_ / 128, MROWS / 128);
    dim3 gF(FF_ / 128, MROWS / 128);
    dim3 gQKV(12, MROWS / 128);

    for (int i = 0; i < L_; i++) {
        size_t wC = (size_t)i * C_ * C_;
        size_t wF = (size_t)i * FF_ * C_;

        tc_qkv_kernel<<<gQKV, 256, DSMEM_SZ>>>(
            Hhi, Hlo,
            Whi + OW_Q + wC, Wlo + OW_Q + wC, bq + i * C_,
            Whi + OW_K + wC, Wlo + OW_K + wC, bk + i * C_,
            Whi + OW_V + wC, Wlo + OW_V + wC, bv + i * C_,
            qhi, qlo, khi, klo, vhi, vlo);

        attn_tc_kernel<<<dim3(S_ / 64, B_ * NH_), 128, ATT_SMEM>>>(
            qhi, qlo, khi, klo, vhi, vlo, ATThi, ATTlo);

        tc_gemm_kernel<<<gC, 256, DSMEM_SZ>>>(
            ATThi, ATTlo, Whi + OW_O + wC, Wlo + OW_O + wC,
            bo + i * C_, H, tmp, nullptr, nullptr, C_, C_, 0, 0);
        ln_kernel<<<MROWS, 128>>>(tmp, H, Hhi, Hlo, g1 + i * C_, bt1 + i * C_);

        tc_gemm_kernel<<<gF, 256, DSMEM_SZ>>>(
            Hhi, Hlo, Whi + OW_1 + wF, Wlo + OW_1 + wF,
            b1 + i * FF_, nullptr, nullptr, FFhi, FFlo, FF_, C_, 1, 0);

        tc_gemm_kernel<<<gC, 256, DSMEM_SZ>>>(
            FFhi, FFlo, Whi + OW_2 + wF, Wlo + OW_2 + wF,
            b2 + i * C_, H, tmp, nullptr, nullptr, C_, FF_, 0, 0);
        ln_kernel<<<MROWS, 128>>>(tmp, H, Hhi, Hlo, g2 + i * C_, bt2 + i * C_);
    }

    heads_kernel<<<B_ * T_, 256>>>(H, Wps, bps, Wpa, bpa, (float*)d_out);
}

// round 12
// speedup vs baseline: 1.2507x; 1.2360x over previous
#include <cuda_runtime.h>
#include <cuda_fp16.h>
#include <math.h>
#include <stdint.h>

// Problem constants
#define B_     8
#define T_     512
#define C_     512
#define L_     4
#define NH_    8
#define DH_    64
#define S_     1024
#define MROWS  8192
#define FF_    2048
#define SD_    48
#define AD_    12

typedef __half h16;

// ---------------------------------------------------------------------------
// Static scratch
// ---------------------------------------------------------------------------
__device__ float g_H  [MROWS * C_];
__device__ float g_tmp[MROWS * C_];

__device__ h16 g_Hhi [MROWS * C_],  g_Hlo [MROWS * C_];
__device__ h16 g_ATThi[MROWS * C_], g_ATTlo[MROWS * C_];
__device__ h16 g_FFhi[MROWS * FF_], g_FFlo[MROWS * FF_];

__device__ h16 g_qhi[MROWS * C_], g_qlo[MROWS * C_];
__device__ h16 g_khi[MROWS * C_];
__device__ h16 g_vhi[MROWS * C_];

#define OW_Q 0
#define OW_K (L_ * C_ * C_)
#define OW_V (2 * L_ * C_ * C_)
#define OW_O (3 * L_ * C_ * C_)
#define OW_1 (4 * L_ * C_ * C_)
#define OW_2 (4 * L_ * C_ * C_ + L_ * FF_ * C_)
#define WTOT (4 * L_ * C_ * C_ + 2 * L_ * FF_ * C_)
__device__ h16 g_Whi[WTOT];

// ---------------------------------------------------------------------------
// PTX helpers (sm_80-era, valid on plain sm_100 target)
// ---------------------------------------------------------------------------
__device__ __forceinline__ uint32_t smem_u32(const void* p) {
    uint32_t a;
    asm("{ .reg .u64 t; cvta.to.shared.u64 t, %1; cvt.u32.u64 %0, t; }"
        : "=r"(a) : "l"(p));
    return a;
}

#define CP16(dst, src) \
    asm volatile("cp.async.cg.shared.global [%0], [%1], 16;" \
                 :: "r"(dst), "l"(src) : "memory")
#define CP_COMMIT()  asm volatile("cp.async.commit_group;" ::: "memory")
#define CP_WAIT1()   asm volatile("cp.async.wait_group 1;" ::: "memory")
#define CP_WAIT0()   asm volatile("cp.async.wait_group 0;" ::: "memory")

#define LDM_X4(r0, r1, r2, r3, addr) \
    asm volatile("ldmatrix.sync.aligned.m8n8.x4.shared.b16 {%0,%1,%2,%3}, [%4];" \
                 : "=r"(r0), "=r"(r1), "=r"(r2), "=r"(r3) : "r"(addr))

#define LDM_X4_T(r0, r1, r2, r3, addr) \
    asm volatile("ldmatrix.sync.aligned.m8n8.x4.trans.shared.b16 {%0,%1,%2,%3}, [%4];" \
                 : "=r"(r0), "=r"(r1), "=r"(r2), "=r"(r3) : "r"(addr))

#define MMA_F16(c, a, b) \
    asm volatile("mma.sync.aligned.m16n8k16.row.col.f32.f16.f16.f32 " \
                 "{%0,%1,%2,%3}, {%4,%5,%6,%7}, {%8,%9}, {%0,%1,%2,%3};" \
                 : "+f"((c)[0]), "+f"((c)[1]), "+f"((c)[2]), "+f"((c)[3]) \
                 : "r"((a)[0]), "r"((a)[1]), "r"((a)[2]), "r"((a)[3]), \
                   "r"((b)[0]), "r"((b)[1]))

__device__ __forceinline__ void split2(float v, h16& h, h16& l) {
    h = __float2half_rn(v);
    l = __float2half_rn(v - __half2float(h));
}

__device__ __forceinline__ void packsplit(float a, float b, uint32_t& ph, uint32_t& pl) {
    __half2 h2, l2;
    h16 ha, la, hb, lb;
    split2(a, ha, la); split2(b, hb, lb);
    h2.x = ha; h2.y = hb; l2.x = la; l2.y = lb;
    ph = *(uint32_t*)&h2; pl = *(uint32_t*)&l2;
}

__device__ __forceinline__ uint32_t packh2(float a, float b) {
    __half2 h2;
    h2.x = __float2half_rn(a); h2.y = __float2half_rn(b);
    return *(uint32_t*)&h2;
}

// ---------------------------------------------------------------------------
// Merged fp32 -> fp16 converter for all six weight groups (hi only)
// ---------------------------------------------------------------------------
#define CS_Q (L_ * C_ * C_ / 4)
#define CS_W1 (L_ * FF_ * C_ / 4)
#define CTOT4 (4 * CS_Q + 2 * CS_W1)

__global__ __launch_bounds__(256) void convert6_kernel(
    const float* __restrict__ Wq, const float* __restrict__ Wk,
    const float* __restrict__ Wv, const float* __restrict__ Wo,
    const float* __restrict__ W1, const float* __restrict__ W2,
    h16* __restrict__ hi)
{
    for (int i = blockIdx.x * 256 + threadIdx.x; i < CTOT4; i += gridDim.x * 256) {
        const float* src;
        int li;
        if      (i < CS_Q)      { src = Wq; li = i; }
        else if (i < 2 * CS_Q)  { src = Wk; li = i - CS_Q; }
        else if (i < 3 * CS_Q)  { src = Wv; li = i - 2 * CS_Q; }
        else if (i < 4 * CS_Q)  { src = Wo; li = i - 3 * CS_Q; }
        else if (i < 4 * CS_Q + CS_W1) { src = W1; li = i - 4 * CS_Q; }
        else                    { src = W2; li = i - 4 * CS_Q - CS_W1; }
        float4 v = ((const float4*)src)[li];
        ((uint2*)hi)[i] = make_uint2(packh2(v.x, v.y), packh2(v.z, v.w));
    }
}

// ---------------------------------------------------------------------------
// Tensor-core GEMM:  out = (Ahi+Alo)[M,K] @ Wh[Nn,K]^T, 2 fp16 MMAs per acc.
// BM=BN=128, BK=32, 256 threads, warp grid 4(m) x 2(n), 2 CTAs/SM.
// ---------------------------------------------------------------------------
#define RS_B    80
#define TILE_B  (128 * RS_B)
#define STAGE_B (3 * TILE_B)       // Ahi, Alo, Wh
#define DSMEM_SZ (2 * STAGE_B)     // 61440

__device__ __forceinline__ void issue_stage(
    const h16* __restrict__ Ahi, const h16* __restrict__ Alo,
    const h16* __restrict__ Bh,
    int m0, int n0, int K, int k0, uint32_t sstage, int tid)
{
#pragma unroll
    for (int it = 0; it < 6; it++) {
        int id  = tid + it * 256;
        int mat = id >> 9;
        int rem = id & 511;
        int r   = rem >> 2;
        int c   = rem & 3;
        const h16* src = (mat == 0) ? Ahi : (mat == 1) ? Alo : Bh;
        int rowbase = (mat < 2) ? m0 : n0;
        const h16* gp = src + (size_t)(rowbase + r) * K + k0 + c * 8;
        uint32_t dst = sstage + mat * TILE_B + r * RS_B + c * 16;
        CP16(dst, gp);
    }
    CP_COMMIT();
}

__device__ __forceinline__ void tc_gemm_body(
    const h16* __restrict__ Ahi, const h16* __restrict__ Alo,
    const h16* __restrict__ Bh,
    const float* __restrict__ bias, const float* __restrict__ resid,
    float* __restrict__ outF, h16* __restrict__ outHi, h16* __restrict__ outLo,
    int Nn, int K, int gelu, int headLayout, float oscale, int bx, int by)
{
    extern __shared__ char dsm[];
    uint32_t sbase = smem_u32(dsm);

    int tid  = threadIdx.x;
    int lane = tid & 31;
    int wid  = tid >> 5;
    int wm0  = (wid & 3) * 32;
    int wn0  = (wid >> 2) * 64;
    int m0   = by * 128;
    int n0   = bx * 128;

    float acc[2][8][4];
#pragma unroll
    for (int mt = 0; mt < 2; mt++)
#pragma unroll
        for (int nf = 0; nf < 8; nf++)
#pragma unroll
            for (int e = 0; e < 4; e++) acc[mt][nf][e] = 0.f;

    int S = K >> 5;

    issue_stage(Ahi, Alo, Bh, m0, n0, K, 0, sbase, tid);

    int aRow = wm0 + (lane & 15);
    int aColB = ((lane >> 4) * 8) * 2;
    int bRowOff = (lane & 7) + ((lane >> 4) << 3);
    int bColB = (((lane >> 3) & 1) * 8) * 2;

    for (int s = 0; s < S; s++) {
        if (s + 1 < S) {
            issue_stage(Ahi, Alo, Bh, m0, n0, K, (s + 1) << 5,
                        sbase + ((s + 1) & 1) * STAGE_B, tid);
            CP_WAIT1();
        } else {
            CP_WAIT0();
        }
        __syncthreads();

        uint32_t st  = sbase + (s & 1) * STAGE_B;
        uint32_t sAh = st;
        uint32_t sAl = st + TILE_B;
        uint32_t sBh = st + 2 * TILE_B;

#pragma unroll
        for (int kk = 0; kk < 2; kk++) {
            uint32_t kByte = kk * 32;

            uint32_t ah[2][4], al[2][4];
#pragma unroll
            for (int mt = 0; mt < 2; mt++) {
                uint32_t addr = sAh + (aRow + mt * 16) * RS_B + kByte + aColB;
                LDM_X4(ah[mt][0], ah[mt][1], ah[mt][2], ah[mt][3], addr);
                addr = sAl + (aRow + mt * 16) * RS_B + kByte + aColB;
                LDM_X4(al[mt][0], al[mt][1], al[mt][2], al[mt][3], addr);
            }

#pragma unroll
            for (int nt = 0; nt < 4; nt++) {
                uint32_t bh0[2], bh1[2];
                uint32_t addr = sBh + (wn0 + nt * 16 + bRowOff) * RS_B + kByte + bColB;
                LDM_X4(bh0[0], bh0[1], bh1[0], bh1[1], addr);
#pragma unroll
                for (int mt = 0; mt < 2; mt++) {
                    MMA_F16(acc[mt][2 * nt],     ah[mt], bh0);
                    MMA_F16(acc[mt][2 * nt],     al[mt], bh0);
                    MMA_F16(acc[mt][2 * nt + 1], ah[mt], bh1);
                    MMA_F16(acc[mt][2 * nt + 1], al[mt], bh1);
                }
            }
        }
        __syncthreads();
    }

    // epilogue
#pragma unroll
    for (int mt = 0; mt < 2; mt++) {
#pragma unroll
        for (int rr = 0; rr < 2; rr++) {
            int m = m0 + wm0 + mt * 16 + (lane >> 2) + rr * 8;
#pragma unroll
            for (int nf = 0; nf < 8; nf++) {
                int c0 = n0 + wn0 + nf * 8 + (lane & 3) * 2;
                float v0 = (acc[mt][nf][rr * 2 + 0] + bias[c0]) * oscale;
                float v1 = (acc[mt][nf][rr * 2 + 1] + bias[c0 + 1]) * oscale;
                if (resid) {
                    const float2 rv = *(const float2*)(resid + (size_t)m * Nn + c0);
                    v0 += rv.x; v1 += rv.y;
                }
                if (gelu) {
                    v0 = 0.5f * v0 * (1.f + erff(v0 * 0.70710678118654752f));
                    v1 = 0.5f * v1 * (1.f + erff(v1 * 0.70710678118654752f));
                }
                size_t off;
                if (headLayout) {
                    int bb = m >> 10, sR = m & 1023, hd = c0 >> 6, d0 = c0 & 63;
                    off = (((size_t)(bb * NH_ + hd) * S_) + sR) * DH_ + d0;
                } else {
                    off = (size_t)m * Nn + c0;
                }
                if (outF) {
                    *(float2*)(outF + off) = make_float2(v0, v1);
                } else if (outLo) {
                    uint32_t ph, pl;
                    packsplit(v0, v1, ph, pl);
                    *(uint32_t*)(outHi + off) = ph;
                    *(uint32_t*)(outLo + off) = pl;
                } else {
                    *(uint32_t*)(outHi + off) = packh2(v0, v1);
                }
            }
        }
    }
}

__global__ __launch_bounds__(256, 2) void tc_gemm_kernel(
    const h16* Ahi, const h16* Alo, const h16* Bh,
    const float* bias, const float* resid,
    float* outF, h16* outHi, h16* outLo,
    int Nn, int K, int gelu, int headLayout)
{
    tc_gemm_body(Ahi, Alo, Bh, bias, resid, outF, outHi, outLo,
                 Nn, K, gelu, headLayout, 1.0f, blockIdx.x, blockIdx.y);
}

// Fused Q/K/V: grid.x = 12; q split (scaled 0.125), k/v hi only, head layout.
__global__ __launch_bounds__(256, 2) void tc_qkv_kernel(
    const h16* Ahi, const h16* Alo,
    const h16* Wqh, const float* bq,
    const h16* Wkh, const float* bk,
    const h16* Wvh, const float* bv,
    h16* qhi, h16* qlo, h16* khi, h16* vhi)
{
    int which = blockIdx.x >> 2;
    int bx    = blockIdx.x & 3;
    const h16* Bh   = (which == 0) ? Wqh : (which == 1) ? Wkh : Wvh;
    const float* bi = (which == 0) ? bq  : (which == 1) ? bk  : bv;
    h16* oh         = (which == 0) ? qhi : (which == 1) ? khi : vhi;
    h16* ol         = (which == 0) ? qlo : nullptr;
    float sc        = (which == 0) ? 0.125f : 1.0f;
    tc_gemm_body(Ahi, Alo, Bh, bi, nullptr, nullptr, oh, ol,
                 C_, C_, 0, 1, sc, bx, blockIdx.y);
}

// ---------------------------------------------------------------------------
// Tensor-core causal flash attention: 64x64 tiles, 128 threads.
// Q split fp16, K/V single fp16.  smem: Qh, Ql, Kh, Vh (4 x 9216 = 36864).
// ---------------------------------------------------------------------------
#define RSA_B  144
#define AT_QH  0
#define AT_QL  (64 * RSA_B)
#define AT_KH  (2 * 64 * RSA_B)
#define AT_VH  (3 * 64 * RSA_B)
#define ATT_SMEM (4 * 64 * RSA_B)   // 36864

__global__ __launch_bounds__(128) void attn_tc_kernel(
    const h16* __restrict__ Qhi, const h16* __restrict__ Qlo,
    const h16* __restrict__ Khi, const h16* __restrict__ Vhi,
    h16* __restrict__ attHi, h16* __restrict__ attLo)
{
    extern __shared__ char sm[];
    uint32_t sb = smem_u32(sm);

    int tid  = threadIdx.x;
    int lane = tid & 31;
    int wid  = tid >> 5;
    int head = blockIdx.y;
    int q0   = blockIdx.x * 64;
    size_t base = (size_t)head * S_ * DH_;

    // load Q hi/lo: 128 threads cover 2 arrays x 64 rows (full 128B rows)
    {
        int arr = tid & 1, r = tid >> 1;
        const uint4* gq = (const uint4*)((arr ? Qlo : Qhi) + base + (size_t)(q0 + r) * DH_);
        uint4* sq = (uint4*)(sm + (arr ? AT_QL : AT_QH) + r * RSA_B);
#pragma unroll
        for (int e = 0; e < 8; e++) sq[e] = gq[e];
    }
    __syncthreads();

    int aRow = (lane & 15);
    int aCol = (lane >> 4) * 16;
    uint32_t qh[4][4], ql[4][4];
#pragma unroll
    for (int kc = 0; kc < 4; kc++) {
        uint32_t addr = sb + AT_QH + (wid * 16 + aRow) * RSA_B + kc * 32 + aCol;
        LDM_X4(qh[kc][0], qh[kc][1], qh[kc][2], qh[kc][3], addr);
        addr = sb + AT_QL + (wid * 16 + aRow) * RSA_B + kc * 32 + aCol;
        LDM_X4(ql[kc][0], ql[kc][1], ql[kc][2], ql[kc][3], addr);
    }

    int bRow = (lane & 7) + ((lane >> 4) << 3);
    int bCol = ((lane >> 3) & 1) * 16;
    int vRow = (lane & 7) + (((lane >> 3) & 1) << 3);
    int vCol = (lane >> 4) * 16;

    float oa[8][4];
#pragma unroll
    for (int f = 0; f < 8; f++)
#pragma unroll
        for (int e = 0; e < 4; e++) oa[f][e] = 0.f;
    float m0r = -1e30f, m1r = -1e30f, l0r = 0.f, l1r = 0.f;

    int nTiles = blockIdx.x + 1;
    for (int kt = 0; kt < nTiles; kt++) {
        int k0 = kt * 64;
        __syncthreads();
        {
            int arr = tid & 1, r = tid >> 1;
            const uint4* gp = (const uint4*)((arr ? Vhi : Khi) + base + (size_t)(k0 + r) * DH_);
            uint4* sp = (uint4*)(sm + (arr ? AT_VH : AT_KH) + r * RSA_B);
#pragma unroll
            for (int e = 0; e < 8; e++) sp[e] = gp[e];
        }
        __syncthreads();

        // ---- scores S = Q @ K^T  (Qh·K + Ql·K) ----
        float sc[8][4];
#pragma unroll
        for (int f = 0; f < 8; f++)
#pragma unroll
            for (int e = 0; e < 4; e++) sc[f][e] = 0.f;

#pragma unroll
        for (int kc = 0; kc < 4; kc++) {
#pragma unroll
            for (int ntk = 0; ntk < 4; ntk++) {
                uint32_t bh0[2], bh1[2];
                uint32_t addr = sb + AT_KH + (ntk * 16 + bRow) * RSA_B + kc * 32 + bCol;
                LDM_X4(bh0[0], bh0[1], bh1[0], bh1[1], addr);
                MMA_F16(sc[2 * ntk],     qh[kc], bh0);
                MMA_F16(sc[2 * ntk],     ql[kc], bh0);
                MMA_F16(sc[2 * ntk + 1], qh[kc], bh1);
                MMA_F16(sc[2 * ntk + 1], ql[kc], bh1);
            }
        }

        if (kt == nTiles - 1) {
            int rg = q0 + wid * 16 + (lane >> 2);
#pragma unroll
            for (int f = 0; f < 8; f++) {
                int c = k0 + f * 8 + (lane & 3) * 2;
                if (c     > rg)     sc[f][0] = -1e30f;
                if (c + 1 > rg)     sc[f][1] = -1e30f;
                if (c     > rg + 8) sc[f][2] = -1e30f;
                if (c + 1 > rg + 8) sc[f][3] = -1e30f;
            }
        }

        float mx0 = -1e30f, mx1 = -1e30f;
#pragma unroll
        for (int f = 0; f < 8; f++) {
            mx0 = fmaxf(mx0, fmaxf(sc[f][0], sc[f][1]));
            mx1 = fmaxf(mx1, fmaxf(sc[f][2], sc[f][3]));
        }
        mx0 = fmaxf(mx0, __shfl_xor_sync(0xffffffffu, mx0, 1));
        mx0 = fmaxf(mx0, __shfl_xor_sync(0xffffffffu, mx0, 2));
        mx1 = fmaxf(mx1, __shfl_xor_sync(0xffffffffu, mx1, 1));
        mx1 = fmaxf(mx1, __shfl_xor_sync(0xffffffffu, mx1, 2));
        float mn0 = fmaxf(m0r, mx0);
        float mn1 = fmaxf(m1r, mx1);

        float sum0 = 0.f, sum1 = 0.f;
#pragma unroll
        for (int f = 0; f < 8; f++) {
            sc[f][0] = __expf(sc[f][0] - mn0);
            sc[f][1] = __expf(sc[f][1] - mn0);
            sc[f][2] = __expf(sc[f][2] - mn1);
            sc[f][3] = __expf(sc[f][3] - mn1);
            sum0 += sc[f][0] + sc[f][1];
            sum1 += sc[f][2] + sc[f][3];
        }
        sum0 += __shfl_xor_sync(0xffffffffu, sum0, 1);
        sum0 += __shfl_xor_sync(0xffffffffu, sum0, 2);
        sum1 += __shfl_xor_sync(0xffffffffu, sum1, 1);
        sum1 += __shfl_xor_sync(0xffffffffu, sum1, 2);

        float cr0 = __expf(m0r - mn0);
        float cr1 = __expf(m1r - mn1);
        l0r = l0r * cr0 + sum0;
        l1r = l1r * cr1 + sum1;
        m0r = mn0; m1r = mn1;
#pragma unroll
        for (int f = 0; f < 8; f++) {
            oa[f][0] *= cr0; oa[f][1] *= cr0;
            oa[f][2] *= cr1; oa[f][3] *= cr1;
        }

        // ---- O += P @ V  (Ph·V + Pl·V) ----
#pragma unroll
        for (int kc = 0; kc < 4; kc++) {
            uint32_t ph[4], pl[4];
            packsplit(sc[2 * kc][0],     sc[2 * kc][1],     ph[0], pl[0]);
            packsplit(sc[2 * kc][2],     sc[2 * kc][3],     ph[1], pl[1]);
            packsplit(sc[2 * kc + 1][0], sc[2 * kc + 1][1], ph[2], pl[2]);
            packsplit(sc[2 * kc + 1][2], sc[2 * kc + 1][3], ph[3], pl[3]);
#pragma unroll
            for (int nt = 0; nt < 4; nt++) {
                uint32_t vh0[2], vh1[2];
                uint32_t addr = sb + AT_VH + (kc * 16 + vRow) * RSA_B + nt * 32 + vCol;
                LDM_X4_T(vh0[0], vh0[1], vh1[0], vh1[1], addr);
                MMA_F16(oa[2 * nt],     ph, vh0);
                MMA_F16(oa[2 * nt],     pl, vh0);
                MMA_F16(oa[2 * nt + 1], ph, vh1);
                MMA_F16(oa[2 * nt + 1], pl, vh1);
            }
        }
    }

    float inv0 = 1.f / l0r, inv1 = 1.f / l1r;
    int brow = (head >> 3) << 10;
    int ncol = (head & 7) << 6;
    int r0   = q0 + wid * 16 + (lane >> 2);
    size_t off0 = (size_t)(brow + r0) * C_ + ncol + (lane & 3) * 2;
    size_t off1 = off0 + (size_t)8 * C_;
#pragma unroll
    for (int f = 0; f < 8; f++) {
        uint32_t ph, pl;
        packsplit(oa[f][0] * inv0, oa[f][1] * inv0, ph, pl);
        *(uint32_t*)(attHi + off0 + f * 8) = ph;
        *(uint32_t*)(attLo + off0 + f * 8) = pl;
        packsplit(oa[f][2] * inv1, oa[f][3] * inv1, ph, pl);
        *(uint32_t*)(attHi + off1 + f * 8) = ph;
        *(uint32_t*)(attLo + off1 + f * 8) = pl;
    }
}

// ---------------------------------------------------------------------------
// Embedding + interleave + LayerNorm (fp32 + fp16 split out)
// ---------------------------------------------------------------------------
__global__ __launch_bounds__(256) void embed_kernel(
    const float* __restrict__ states, const float* __restrict__ actions,
    const float* __restrict__ We_s, const float* __restrict__ be_s,
    const float* __restrict__ We_a, const float* __restrict__ be_a,
    const float* __restrict__ pe,
    const float* __restrict__ g, const float* __restrict__ bt,
    float* __restrict__ H, h16* __restrict__ Hhi, h16* __restrict__ Hlo)
{
    __shared__ float xs[SD_];
    __shared__ float rs[256], rq[256];

    int row = blockIdx.x;
    int b   = row >> 10;
    int s   = row & 1023;
    int t   = s >> 1;
    int act = s & 1;
    int tid = threadIdx.x;

    int K            = act ? AD_ : SD_;
    const float* x   = act ? (actions + ((size_t)b * T_ + t) * AD_)
                           : (states  + ((size_t)b * T_ + t) * SD_);
    const float* W   = act ? We_a : We_s;
    const float* bia = act ? be_a : be_s;

    if (tid < K) xs[tid] = x[tid];
    __syncthreads();

    float v[2];
    float sum = 0.f, sumsq = 0.f;
#pragma unroll
    for (int e = 0; e < 2; e++) {
        int c = tid + e * 256;
        float a = bia[c] + pe[t * C_ + c];
        const float* wr = W + (size_t)c * K;
        for (int k = 0; k < K; k++) a += xs[k] * wr[k];
        v[e] = a;
        sum += a; sumsq += a * a;
    }
    rs[tid] = sum; rq[tid] = sumsq;
    __syncthreads();
    for (int off = 128; off > 0; off >>= 1) {
        if (tid < off) { rs[tid] += rs[tid + off]; rq[tid] += rq[tid + off]; }
        __syncthreads();
    }
    float mean = rs[0] * (1.f / C_);
    float var  = rq[0] * (1.f / C_) - mean * mean;
    float rstd = rsqrtf(var + 1e-5f);

#pragma unroll
    for (int e = 0; e < 2; e++) {
        int c = tid + e * 256;
        float y = (v[e] - mean) * rstd * g[c] + bt[c];
        size_t o = (size_t)row * C_ + c;
        H[o] = y;
        h16 h, l; split2(y, h, l);
        Hhi[o] = h; Hlo[o] = l;
    }
}

// ---------------------------------------------------------------------------
// LayerNorm — 128 threads/row, float4 + warp shuffles
// ---------------------------------------------------------------------------
__global__ __launch_bounds__(128) void ln_kernel(
    const float* __restrict__ in, float* __restrict__ out,
    h16* __restrict__ outHi, h16* __restrict__ outLo,
    const float* __restrict__ g, const float* __restrict__ bt)
{
    __shared__ float ws[4], wq[4];
    int row  = blockIdx.x;
    int tid  = threadIdx.x;
    int lane = tid & 31;
    int wd   = tid >> 5;

    float4 v = ((const float4*)(in + (size_t)row * C_))[tid];
    float sum = v.x + v.y + v.z + v.w;
    float sq  = v.x * v.x + v.y * v.y + v.z * v.z + v.w * v.w;
#pragma unroll
    for (int off = 16; off > 0; off >>= 1) {
        sum += __shfl_xor_sync(0xffffffffu, sum, off);
        sq  += __shfl_xor_sync(0xffffffffu, sq,  off);
    }
    if (lane == 0) { ws[wd] = sum; wq[wd] = sq; }
    __syncthreads();
    sum = ws[0] + ws[1] + ws[2] + ws[3];
    sq  = wq[0] + wq[1] + wq[2] + wq[3];

    float mean = sum * (1.f / C_);
    float var  = sq * (1.f / C_) - mean * mean;
    float rstd = rsqrtf(var + 1e-5f);

    float4 gv = ((const float4*)g)[tid];
    float4 bv = ((const float4*)bt)[tid];
    float4 y;
    y.x = (v.x - mean) * rstd * gv.x + bv.x;
    y.y = (v.y - mean) * rstd * gv.y + bv.y;
    y.z = (v.z - mean) * rstd * gv.z + bv.z;
    y.w = (v.w - mean) * rstd * gv.w + bv.w;

    ((float4*)(out + (size_t)row * C_))[tid] = y;
    uint32_t h01, l01, h23, l23;
    packsplit(y.x, y.y, h01, l01);
    packsplit(y.z, y.w, h23, l23);
    ((uint2*)(outHi + (size_t)row * C_))[tid] = make_uint2(h01, h23);
    ((uint2*)(outLo + (size_t)row * C_))[tid] = make_uint2(l01, l23);
}

// ---------------------------------------------------------------------------
// Output heads — 4 threads per output, quad shuffle reduce (fp32)
// ---------------------------------------------------------------------------
__global__ __launch_bounds__(256) void heads_kernel(
    const float* __restrict__ H,
    const float* __restrict__ Wps, const float* __restrict__ bps,
    const float* __restrict__ Wpa, const float* __restrict__ bpa,
    float* __restrict__ out)
{
    __shared__ float rows[2 * C_];
    int bt  = blockIdx.x;
    int b   = bt >> 9;
    int t   = bt & 511;
    int tid = threadIdx.x;

    size_t base = ((size_t)(b << 10) + (t << 1)) * C_;
    ((float4*)rows)[tid] = ((const float4*)(H + base))[tid];
    __syncthreads();

    int o   = tid >> 2;
    int sub = tid & 3;
    if (o < SD_ + AD_) {
        const float* w;
        const float* r;
        if (o < SD_) { w = Wps + (size_t)o * C_;          r = rows + C_; }
        else         { w = Wpa + (size_t)(o - SD_) * C_;  r = rows; }
        float a = 0.f;
        int k0 = sub * 128;
#pragma unroll 4
        for (int k = 0; k < 128; k++) a += r[k0 + k] * w[k0 + k];
        a += __shfl_xor_sync(0xffffffffu, a, 1);
        a += __shfl_xor_sync(0xffffffffu, a, 2);
        if (sub == 0) {
            if (o < SD_) out[(size_t)bt * SD_ + o] = a + bps[o];
            else out[(size_t)(B_ * T_ * SD_) + (size_t)bt * AD_ + (o - SD_)] = a + bpa[o - SD_];
        }
    }
}

// ---------------------------------------------------------------------------
// Launch
// ---------------------------------------------------------------------------
extern "C" void kernel_launch(void* const* d_in, const int* in_sizes, int n_in,
                              void* d_out, int out_size)
{
    const float* states  = (const float*)d_in[0];
    const float* actions = (const float*)d_in[1];
    const float* We_s    = (const float*)d_in[2];
    const float* be_s    = (const float*)d_in[3];
    const float* We_a    = (const float*)d_in[4];
    const float* be_a    = (const float*)d_in[5];
    const float* pe      = (const float*)d_in[6];
    const float* g_emb   = (const float*)d_in[7];
    const float* b_emb   = (const float*)d_in[8];
    const float* Wq      = (const float*)d_in[9];
    const float* bq      = (const float*)d_in[10];
    const float* Wk      = (const float*)d_in[11];
    const float* bk      = (const float*)d_in[12];
    const float* Wv      = (const float*)d_in[13];
    const float* bv      = (const float*)d_in[14];
    const float* Wo      = (const float*)d_in[15];
    const float* bo      = (const float*)d_in[16];
    const float* W1      = (const float*)d_in[17];
    const float* b1      = (const float*)d_in[18];
    const float* W2      = (const float*)d_in[19];
    const float* b2      = (const float*)d_in[20];
    const float* g1      = (const float*)d_in[21];
    const float* bt1     = (const float*)d_in[22];
    const float* g2      = (const float*)d_in[23];
    const float* bt2     = (const float*)d_in[24];
    const float* Wps     = (const float*)d_in[25];
    const float* bps     = (const float*)d_in[26];
    const float* Wpa     = (const float*)d_in[27];
    const float* bpa     = (const float*)d_in[28];

    float *H, *tmp;
    h16 *Hhi, *Hlo, *ATThi, *ATTlo, *FFhi, *FFlo, *Whi;
    h16 *qhi, *qlo, *khi, *vhi;
    cudaGetSymbolAddress((void**)&H,    g_H);
    cudaGetSymbolAddress((void**)&tmp,  g_tmp);
    cudaGetSymbolAddress((void**)&Hhi,  g_Hhi);
    cudaGetSymbolAddress((void**)&Hlo,  g_Hlo);
    cudaGetSymbolAddress((void**)&ATThi, g_ATThi);
    cudaGetSymbolAddress((void**)&ATTlo, g_ATTlo);
    cudaGetSymbolAddress((void**)&FFhi, g_FFhi);
    cudaGetSymbolAddress((void**)&FFlo, g_FFlo);
    cudaGetSymbolAddress((void**)&Whi,  g_Whi);
    cudaGetSymbolAddress((void**)&qhi,  g_qhi);
    cudaGetSymbolAddress((void**)&qlo,  g_qlo);
    cudaGetSymbolAddress((void**)&khi,  g_khi);
    cudaGetSymbolAddress((void**)&vhi,  g_vhi);

    cudaFuncSetAttribute(tc_gemm_kernel, cudaFuncAttributeMaxDynamicSharedMemorySize, DSMEM_SZ);
    cudaFuncSetAttribute(tc_qkv_kernel,  cudaFuncAttributeMaxDynamicSharedMemorySize, DSMEM_SZ);
    cudaFuncSetAttribute(attn_tc_kernel, cudaFuncAttributeMaxDynamicSharedMemorySize, ATT_SMEM);

    convert6_kernel<<<4096, 256>>>(Wq, Wk, Wv, Wo, W1, W2, Whi);

    embed_kernel<<<MROWS, 256>>>(states, actions, We_s, be_s, We_a, be_a,
                                 pe, g_emb, b_emb, H, Hhi, Hlo);

    dim3 gC(C_ / 128, MROWS / 128);
    dim3 gF(FF_ / 128, MROWS / 128);
    dim3 gQKV(12, MROWS / 128);

    for (int i = 0; i < L_; i++) {
        size_t wC = (size_t)i * C_ * C_;
        size_t wF = (size_t)i * FF_ * C_;

        tc_qkv_kernel<<<gQKV, 256, DSMEM_SZ>>>(
            Hhi, Hlo,
            Whi + OW_Q + wC, bq + i * C_,
            Whi + OW_K + wC, bk + i * C_,
            Whi + OW_V + wC, bv + i * C_,
            qhi, qlo, khi, vhi);

        attn_tc_kernel<<<dim3(S_ / 64, B_ * NH_), 128, ATT_SMEM>>>(
            qhi, qlo, khi, vhi, ATThi, ATTlo);

        tc_gemm_kernel<<<gC, 256, DSMEM_SZ>>>(
            ATThi, ATTlo, Whi + OW_O + wC,
            bo + i * C_, H, tmp, nullptr, nullptr, C_, C_, 0, 0);
        ln_kernel<<<MROWS, 128>>>(tmp, H, Hhi, Hlo, g1 + i * C_, bt1 + i * C_);

        tc_gemm_kernel<<<gF, 256, DSMEM_SZ>>>(
            Hhi, Hlo, Whi + OW_1 + wF,
            b1 + i * FF_, nullptr, nullptr, FFhi, FFlo, FF_, C_, 1, 0);

        tc_gemm_kernel<<<gC, 256, DSMEM_SZ>>>(
            FFhi, FFlo, Whi + OW_2 + wF,
            b2 + i * C_, H, tmp, nullptr, nullptr, C_, FF_, 0, 0);
        ln_kernel<<<MROWS, 128>>>(tmp, H, Hhi, Hlo, g2 + i * C_, bt2 + i * C_);
    }

    heads_kernel<<<B_ * T_, 256>>>(H, Wps, bps, Wpa, bpa, (float*)d_out);
}

// round 13
// speedup vs baseline: 1.6133x; 1.2899x over previous
#include <cuda_runtime.h>
#include <cuda_fp16.h>
#include <math.h>
#include <stdint.h>

// Problem constants
#define B_     8
#define T_     512
#define C_     512
#define L_     4
#define NH_    8
#define DH_    64
#define S_     1024
#define MROWS  8192
#define FF_    2048
#define SD_    48
#define AD_    12

typedef __half h16;

// ---------------------------------------------------------------------------
// Static scratch
// ---------------------------------------------------------------------------
__device__ float g_H  [MROWS * C_];
__device__ float g_tmp[MROWS * C_];

__device__ h16 g_Hhi [MROWS * C_];
__device__ h16 g_ATThi[MROWS * C_];
__device__ h16 g_FFhi[MROWS * FF_];

__device__ h16 g_qhi[MROWS * C_], g_qlo[MROWS * C_];
__device__ h16 g_khi[MROWS * C_];
__device__ h16 g_vhi[MROWS * C_];

#define OW_Q 0
#define OW_K (L_ * C_ * C_)
#define OW_V (2 * L_ * C_ * C_)
#define OW_O (3 * L_ * C_ * C_)
#define OW_1 (4 * L_ * C_ * C_)
#define OW_2 (4 * L_ * C_ * C_ + L_ * FF_ * C_)
#define WTOT (4 * L_ * C_ * C_ + 2 * L_ * FF_ * C_)
__device__ h16 g_Whi[WTOT];

// ---------------------------------------------------------------------------
// PTX helpers (sm_80-era, valid on plain sm_100 target)
// ---------------------------------------------------------------------------
__device__ __forceinline__ uint32_t smem_u32(const void* p) {
    uint32_t a;
    asm("{ .reg .u64 t; cvta.to.shared.u64 t, %1; cvt.u32.u64 %0, t; }"
        : "=r"(a) : "l"(p));
    return a;
}

#define CP16(dst, src) \
    asm volatile("cp.async.cg.shared.global [%0], [%1], 16;" \
                 :: "r"(dst), "l"(src) : "memory")
#define CP_COMMIT()  asm volatile("cp.async.commit_group;" ::: "memory")
#define CP_WAIT1()   asm volatile("cp.async.wait_group 1;" ::: "memory")
#define CP_WAIT0()   asm volatile("cp.async.wait_group 0;" ::: "memory")

#define LDM_X4(r0, r1, r2, r3, addr) \
    asm volatile("ldmatrix.sync.aligned.m8n8.x4.shared.b16 {%0,%1,%2,%3}, [%4];" \
                 : "=r"(r0), "=r"(r1), "=r"(r2), "=r"(r3) : "r"(addr))

#define LDM_X4_T(r0, r1, r2, r3, addr) \
    asm volatile("ldmatrix.sync.aligned.m8n8.x4.trans.shared.b16 {%0,%1,%2,%3}, [%4];" \
                 : "=r"(r0), "=r"(r1), "=r"(r2), "=r"(r3) : "r"(addr))

#define MMA_F16(c, a, b) \
    asm volatile("mma.sync.aligned.m16n8k16.row.col.f32.f16.f16.f32 " \
                 "{%0,%1,%2,%3}, {%4,%5,%6,%7}, {%8,%9}, {%0,%1,%2,%3};" \
                 : "+f"((c)[0]), "+f"((c)[1]), "+f"((c)[2]), "+f"((c)[3]) \
                 : "r"((a)[0]), "r"((a)[1]), "r"((a)[2]), "r"((a)[3]), \
                   "r"((b)[0]), "r"((b)[1]))

__device__ __forceinline__ void split2(float v, h16& h, h16& l) {
    h = __float2half_rn(v);
    l = __float2half_rn(v - __half2float(h));
}

__device__ __forceinline__ void packsplit(float a, float b, uint32_t& ph, uint32_t& pl) {
    __half2 h2, l2;
    h16 ha, la, hb, lb;
    split2(a, ha, la); split2(b, hb, lb);
    h2.x = ha; h2.y = hb; l2.x = la; l2.y = lb;
    ph = *(uint32_t*)&h2; pl = *(uint32_t*)&l2;
}

__device__ __forceinline__ uint32_t packh2(float a, float b) {
    __half2 h2;
    h2.x = __float2half_rn(a); h2.y = __float2half_rn(b);
    return *(uint32_t*)&h2;
}

// ---------------------------------------------------------------------------
// Merged fp32 -> fp16 converter for all six weight groups
// ---------------------------------------------------------------------------
#define CS_Q (L_ * C_ * C_ / 4)
#define CS_W1 (L_ * FF_ * C_ / 4)
#define CTOT4 (4 * CS_Q + 2 * CS_W1)

__global__ __launch_bounds__(256) void convert6_kernel(
    const float* __restrict__ Wq, const float* __restrict__ Wk,
    const float* __restrict__ Wv, const float* __restrict__ Wo,
    const float* __restrict__ W1, const float* __restrict__ W2,
    h16* __restrict__ hi)
{
    for (int i = blockIdx.x * 256 + threadIdx.x; i < CTOT4; i += gridDim.x * 256) {
        const float* src;
        int li;
        if      (i < CS_Q)      { src = Wq; li = i; }
        else if (i < 2 * CS_Q)  { src = Wk; li = i - CS_Q; }
        else if (i < 3 * CS_Q)  { src = Wv; li = i - 2 * CS_Q; }
        else if (i < 4 * CS_Q)  { src = Wo; li = i - 3 * CS_Q; }
        else if (i < 4 * CS_Q + CS_W1) { src = W1; li = i - 4 * CS_Q; }
        else                    { src = W2; li = i - 4 * CS_Q - CS_W1; }
        float4 v = ((const float4*)src)[li];
        ((uint2*)hi)[i] = make_uint2(packh2(v.x, v.y), packh2(v.z, v.w));
    }
}

// ---------------------------------------------------------------------------
// Tensor-core GEMM:  out = A[M,K] @ W[Nn,K]^T, single fp16, 1 MMA per acc.
// BM=BN=128, BK=32, 256 threads, warp grid 4(m) x 2(n), 2 CTAs/SM.
// ---------------------------------------------------------------------------
#define RS_B    80
#define TILE_B  (128 * RS_B)
#define STAGE_B (2 * TILE_B)       // A, W
#define DSMEM_SZ (2 * STAGE_B)     // 40960

__device__ __forceinline__ void issue_stage(
    const h16* __restrict__ Ah, const h16* __restrict__ Bh,
    int m0, int n0, int K, int k0, uint32_t sstage, int tid)
{
#pragma unroll
    for (int it = 0; it < 4; it++) {
        int id  = tid + it * 256;
        int mat = id >> 9;
        int rem = id & 511;
        int r   = rem >> 2;
        int c   = rem & 3;
        const h16* src = mat ? Bh : Ah;
        int rowbase = mat ? n0 : m0;
        const h16* gp = src + (size_t)(rowbase + r) * K + k0 + c * 8;
        uint32_t dst = sstage + mat * TILE_B + r * RS_B + c * 16;
        CP16(dst, gp);
    }
    CP_COMMIT();
}

__device__ __forceinline__ void tc_gemm_body(
    const h16* __restrict__ Ah, const h16* __restrict__ Bh,
    const float* __restrict__ bias, const float* __restrict__ resid,
    float* __restrict__ outF, h16* __restrict__ outHi, h16* __restrict__ outLo,
    int Nn, int K, int gelu, int headLayout, float oscale, int bx, int by)
{
    extern __shared__ char dsm[];
    uint32_t sbase = smem_u32(dsm);

    int tid  = threadIdx.x;
    int lane = tid & 31;
    int wid  = tid >> 5;
    int wm0  = (wid & 3) * 32;
    int wn0  = (wid >> 2) * 64;
    int m0   = by * 128;
    int n0   = bx * 128;

    float acc[2][8][4];
#pragma unroll
    for (int mt = 0; mt < 2; mt++)
#pragma unroll
        for (int nf = 0; nf < 8; nf++)
#pragma unroll
            for (int e = 0; e < 4; e++) acc[mt][nf][e] = 0.f;

    int S = K >> 5;

    issue_stage(Ah, Bh, m0, n0, K, 0, sbase, tid);

    int aRow = wm0 + (lane & 15);
    int aColB = ((lane >> 4) * 8) * 2;
    int bRowOff = (lane & 7) + ((lane >> 4) << 3);
    int bColB = (((lane >> 3) & 1) * 8) * 2;

    for (int s = 0; s < S; s++) {
        if (s + 1 < S) {
            issue_stage(Ah, Bh, m0, n0, K, (s + 1) << 5,
                        sbase + ((s + 1) & 1) * STAGE_B, tid);
            CP_WAIT1();
        } else {
            CP_WAIT0();
        }
        __syncthreads();

        uint32_t st  = sbase + (s & 1) * STAGE_B;
        uint32_t sAh = st;
        uint32_t sBh = st + TILE_B;

#pragma unroll
        for (int kk = 0; kk < 2; kk++) {
            uint32_t kByte = kk * 32;

            uint32_t ah[2][4];
#pragma unroll
            for (int mt = 0; mt < 2; mt++) {
                uint32_t addr = sAh + (aRow + mt * 16) * RS_B + kByte + aColB;
                LDM_X4(ah[mt][0], ah[mt][1], ah[mt][2], ah[mt][3], addr);
            }

#pragma unroll
            for (int nt = 0; nt < 4; nt++) {
                uint32_t bh0[2], bh1[2];
                uint32_t addr = sBh + (wn0 + nt * 16 + bRowOff) * RS_B + kByte + bColB;
                LDM_X4(bh0[0], bh0[1], bh1[0], bh1[1], addr);
#pragma unroll
                for (int mt = 0; mt < 2; mt++) {
                    MMA_F16(acc[mt][2 * nt],     ah[mt], bh0);
                    MMA_F16(acc[mt][2 * nt + 1], ah[mt], bh1);
                }
            }
        }
        __syncthreads();
    }

    // epilogue
#pragma unroll
    for (int mt = 0; mt < 2; mt++) {
#pragma unroll
        for (int rr = 0; rr < 2; rr++) {
            int m = m0 + wm0 + mt * 16 + (lane >> 2) + rr * 8;
#pragma unroll
            for (int nf = 0; nf < 8; nf++) {
                int c0 = n0 + wn0 + nf * 8 + (lane & 3) * 2;
                float v0 = (acc[mt][nf][rr * 2 + 0] + bias[c0]) * oscale;
                float v1 = (acc[mt][nf][rr * 2 + 1] + bias[c0 + 1]) * oscale;
                if (resid) {
                    const float2 rv = *(const float2*)(resid + (size_t)m * Nn + c0);
                    v0 += rv.x; v1 += rv.y;
                }
                if (gelu) {
                    v0 = 0.5f * v0 * (1.f + erff(v0 * 0.70710678118654752f));
                    v1 = 0.5f * v1 * (1.f + erff(v1 * 0.70710678118654752f));
                }
                size_t off;
                if (headLayout) {
                    int bb = m >> 10, sR = m & 1023, hd = c0 >> 6, d0 = c0 & 63;
                    off = (((size_t)(bb * NH_ + hd) * S_) + sR) * DH_ + d0;
                } else {
                    off = (size_t)m * Nn + c0;
                }
                if (outF) {
                    *(float2*)(outF + off) = make_float2(v0, v1);
                } else if (outLo) {
                    uint32_t ph, pl;
                    packsplit(v0, v1, ph, pl);
                    *(uint32_t*)(outHi + off) = ph;
                    *(uint32_t*)(outLo + off) = pl;
                } else {
                    *(uint32_t*)(outHi + off) = packh2(v0, v1);
                }
            }
        }
    }
}

__global__ __launch_bounds__(256, 2) void tc_gemm_kernel(
    const h16* Ah, const h16* Bh,
    const float* bias, const float* resid,
    float* outF, h16* outHi, h16* outLo,
    int Nn, int K, int gelu, int headLayout)
{
    tc_gemm_body(Ah, Bh, bias, resid, outF, outHi, outLo,
                 Nn, K, gelu, headLayout, 1.0f, blockIdx.x, blockIdx.y);
}

// Fused Q/K/V: grid.x = 12; q split (scaled 0.125), k/v single, head layout.
__global__ __launch_bounds__(256, 2) void tc_qkv_kernel(
    const h16* Ah,
    const h16* Wqh, const float* bq,
    const h16* Wkh, const float* bk,
    const h16* Wvh, const float* bv,
    h16* qhi, h16* qlo, h16* khi, h16* vhi)
{
    int which = blockIdx.x >> 2;
    int bx    = blockIdx.x & 3;
    const h16* Bh   = (which == 0) ? Wqh : (which == 1) ? Wkh : Wvh;
    const float* bi = (which == 0) ? bq  : (which == 1) ? bk  : bv;
    h16* oh         = (which == 0) ? qhi : (which == 1) ? khi : vhi;
    h16* ol         = (which == 0) ? qlo : nullptr;
    float sc        = (which == 0) ? 0.125f : 1.0f;
    tc_gemm_body(Ah, Bh, bi, nullptr, nullptr, oh, ol,
                 C_, C_, 0, 1, sc, bx, blockIdx.y);
}

// ---------------------------------------------------------------------------
// Tensor-core causal flash attention: 64x64 tiles, 128 threads.
// Q split fp16, K/V single fp16, P split.  smem: Qh, Ql, Kh, Vh.
// ---------------------------------------------------------------------------
#define RSA_B  144
#define AT_QH  0
#define AT_QL  (64 * RSA_B)
#define AT_KH  (2 * 64 * RSA_B)
#define AT_VH  (3 * 64 * RSA_B)
#define ATT_SMEM (4 * 64 * RSA_B)   // 36864

__global__ __launch_bounds__(128) void attn_tc_kernel(
    const h16* __restrict__ Qhi, const h16* __restrict__ Qlo,
    const h16* __restrict__ Khi, const h16* __restrict__ Vhi,
    h16* __restrict__ attHi)
{
    extern __shared__ char sm[];
    uint32_t sb = smem_u32(sm);

    int tid  = threadIdx.x;
    int lane = tid & 31;
    int wid  = tid >> 5;
    int head = blockIdx.y;
    int q0   = blockIdx.x * 64;
    size_t base = (size_t)head * S_ * DH_;

    {
        int arr = tid & 1, r = tid >> 1;
        const uint4* gq = (const uint4*)((arr ? Qlo : Qhi) + base + (size_t)(q0 + r) * DH_);
        uint4* sq = (uint4*)(sm + (arr ? AT_QL : AT_QH) + r * RSA_B);
#pragma unroll
        for (int e = 0; e < 8; e++) sq[e] = gq[e];
    }
    __syncthreads();

    int aRow = (lane & 15);
    int aCol = (lane >> 4) * 16;
    uint32_t qh[4][4], ql[4][4];
#pragma unroll
    for (int kc = 0; kc < 4; kc++) {
        uint32_t addr = sb + AT_QH + (wid * 16 + aRow) * RSA_B + kc * 32 + aCol;
        LDM_X4(qh[kc][0], qh[kc][1], qh[kc][2], qh[kc][3], addr);
        addr = sb + AT_QL + (wid * 16 + aRow) * RSA_B + kc * 32 + aCol;
        LDM_X4(ql[kc][0], ql[kc][1], ql[kc][2], ql[kc][3], addr);
    }

    int bRow = (lane & 7) + ((lane >> 4) << 3);
    int bCol = ((lane >> 3) & 1) * 16;
    int vRow = (lane & 7) + (((lane >> 3) & 1) << 3);
    int vCol = (lane >> 4) * 16;

    float oa[8][4];
#pragma unroll
    for (int f = 0; f < 8; f++)
#pragma unroll
        for (int e = 0; e < 4; e++) oa[f][e] = 0.f;
    float m0r = -1e30f, m1r = -1e30f, l0r = 0.f, l1r = 0.f;

    int nTiles = blockIdx.x + 1;
    for (int kt = 0; kt < nTiles; kt++) {
        int k0 = kt * 64;
        __syncthreads();
        {
            int arr = tid & 1, r = tid >> 1;
            const uint4* gp = (const uint4*)((arr ? Vhi : Khi) + base + (size_t)(k0 + r) * DH_);
            uint4* sp = (uint4*)(sm + (arr ? AT_VH : AT_KH) + r * RSA_B);
#pragma unroll
            for (int e = 0; e < 8; e++) sp[e] = gp[e];
        }
        __syncthreads();

        float sc[8][4];
#pragma unroll
        for (int f = 0; f < 8; f++)
#pragma unroll
            for (int e = 0; e < 4; e++) sc[f][e] = 0.f;

#pragma unroll
        for (int kc = 0; kc < 4; kc++) {
#pragma unroll
            for (int ntk = 0; ntk < 4; ntk++) {
                uint32_t bh0[2], bh1[2];
                uint32_t addr = sb + AT_KH + (ntk * 16 + bRow) * RSA_B + kc * 32 + bCol;
                LDM_X4(bh0[0], bh0[1], bh1[0], bh1[1], addr);
                MMA_F16(sc[2 * ntk],     qh[kc], bh0);
                MMA_F16(sc[2 * ntk],     ql[kc], bh0);
                MMA_F16(sc[2 * ntk + 1], qh[kc], bh1);
                MMA_F16(sc[2 * ntk + 1], ql[kc], bh1);
            }
        }

        if (kt == nTiles - 1) {
            int rg = q0 + wid * 16 + (lane >> 2);
#pragma unroll
            for (int f = 0; f < 8; f++) {
                int c = k0 + f * 8 + (lane & 3) * 2;
                if (c     > rg)     sc[f][0] = -1e30f;
                if (c + 1 > rg)     sc[f][1] = -1e30f;
                if (c     > rg + 8) sc[f][2] = -1e30f;
                if (c + 1 > rg + 8) sc[f][3] = -1e30f;
            }
        }

        float mx0 = -1e30f, mx1 = -1e30f;
#pragma unroll
        for (int f = 0; f < 8; f++) {
            mx0 = fmaxf(mx0, fmaxf(sc[f][0], sc[f][1]));
            mx1 = fmaxf(mx1, fmaxf(sc[f][2], sc[f][3]));
        }
        mx0 = fmaxf(mx0, __shfl_xor_sync(0xffffffffu, mx0, 1));
        mx0 = fmaxf(mx0, __shfl_xor_sync(0xffffffffu, mx0, 2));
        mx1 = fmaxf(mx1, __shfl_xor_sync(0xffffffffu, mx1, 1));
        mx1 = fmaxf(mx1, __shfl_xor_sync(0xffffffffu, mx1, 2));
        float mn0 = fmaxf(m0r, mx0);
        float mn1 = fmaxf(m1r, mx1);

        float sum0 = 0.f, sum1 = 0.f;
#pragma unroll
        for (int f = 0; f < 8; f++) {
            sc[f][0] = __expf(sc[f][0] - mn0);
            sc[f][1] = __expf(sc[f][1] - mn0);
            sc[f][2] = __expf(sc[f][2] - mn1);
            sc[f][3] = __expf(sc[f][3] - mn1);
            sum0 += sc[f][0] + sc[f][1];
            sum1 += sc[f][2] + sc[f][3];
        }
        sum0 += __shfl_xor_sync(0xffffffffu, sum0, 1);
        sum0 += __shfl_xor_sync(0xffffffffu, sum0, 2);
        sum1 += __shfl_xor_sync(0xffffffffu, sum1, 1);
        sum1 += __shfl_xor_sync(0xffffffffu, sum1, 2);

        float cr0 = __expf(m0r - mn0);
        float cr1 = __expf(m1r - mn1);
        l0r = l0r * cr0 + sum0;
        l1r = l1r * cr1 + sum1;
        m0r = mn0; m1r = mn1;
#pragma unroll
        for (int f = 0; f < 8; f++) {
            oa[f][0] *= cr0; oa[f][1] *= cr0;
            oa[f][2] *= cr1; oa[f][3] *= cr1;
        }

#pragma unroll
        for (int kc = 0; kc < 4; kc++) {
            uint32_t ph[4], pl[4];
            packsplit(sc[2 * kc][0],     sc[2 * kc][1],     ph[0], pl[0]);
            packsplit(sc[2 * kc][2],     sc[2 * kc][3],     ph[1], pl[1]);
            packsplit(sc[2 * kc + 1][0], sc[2 * kc + 1][1], ph[2], pl[2]);
            packsplit(sc[2 * kc + 1][2], sc[2 * kc + 1][3], ph[3], pl[3]);
#pragma unroll
            for (int nt = 0; nt < 4; nt++) {
                uint32_t vh0[2], vh1[2];
                uint32_t addr = sb + AT_VH + (kc * 16 + vRow) * RSA_B + nt * 32 + vCol;
                LDM_X4_T(vh0[0], vh0[1], vh1[0], vh1[1], addr);
                MMA_F16(oa[2 * nt],     ph, vh0);
                MMA_F16(oa[2 * nt],     pl, vh0);
                MMA_F16(oa[2 * nt + 1], ph, vh1);
                MMA_F16(oa[2 * nt + 1], pl, vh1);
            }
        }
    }

    float inv0 = 1.f / l0r, inv1 = 1.f / l1r;
    int brow = (head >> 3) << 10;
    int ncol = (head & 7) << 6;
    int r0   = q0 + wid * 16 + (lane >> 2);
    size_t off0 = (size_t)(brow + r0) * C_ + ncol + (lane & 3) * 2;
    size_t off1 = off0 + (size_t)8 * C_;
#pragma unroll
    for (int f = 0; f < 8; f++) {
        *(uint32_t*)(attHi + off0 + f * 8) = packh2(oa[f][0] * inv0, oa[f][1] * inv0);
        *(uint32_t*)(attHi + off1 + f * 8) = packh2(oa[f][2] * inv1, oa[f][3] * inv1);
    }
}

// ---------------------------------------------------------------------------
// Embedding + interleave + LayerNorm (fp32 + fp16 out)
// ---------------------------------------------------------------------------
__global__ __launch_bounds__(256) void embed_kernel(
    const float* __restrict__ states, const float* __restrict__ actions,
    const float* __restrict__ We_s, const float* __restrict__ be_s,
    const float* __restrict__ We_a, const float* __restrict__ be_a,
    const float* __restrict__ pe,
    const float* __restrict__ g, const float* __restrict__ bt,
    float* __restrict__ H, h16* __restrict__ Hhi)
{
    __shared__ float xs[SD_];
    __shared__ float rs[256], rq[256];

    int row = blockIdx.x;
    int b   = row >> 10;
    int s   = row & 1023;
    int t   = s >> 1;
    int act = s & 1;
    int tid = threadIdx.x;

    int K            = act ? AD_ : SD_;
    const float* x   = act ? (actions + ((size_t)b * T_ + t) * AD_)
                           : (states  + ((size_t)b * T_ + t) * SD_);
    const float* W   = act ? We_a : We_s;
    const float* bia = act ? be_a : be_s;

    if (tid < K) xs[tid] = x[tid];
    __syncthreads();

    float v[2];
    float sum = 0.f, sumsq = 0.f;
#pragma unroll
    for (int e = 0; e < 2; e++) {
        int c = tid + e * 256;
        float a = bia[c] + pe[t * C_ + c];
        const float* wr = W + (size_t)c * K;
        for (int k = 0; k < K; k++) a += xs[k] * wr[k];
        v[e] = a;
        sum += a; sumsq += a * a;
    }
    rs[tid] = sum; rq[tid] = sumsq;
    __syncthreads();
    for (int off = 128; off > 0; off >>= 1) {
        if (tid < off) { rs[tid] += rs[tid + off]; rq[tid] += rq[tid + off]; }
        __syncthreads();
    }
    float mean = rs[0] * (1.f / C_);
    float var  = rq[0] * (1.f / C_) - mean * mean;
    float rstd = rsqrtf(var + 1e-5f);

#pragma unroll
    for (int e = 0; e < 2; e++) {
        int c = tid + e * 256;
        float y = (v[e] - mean) * rstd * g[c] + bt[c];
        size_t o = (size_t)row * C_ + c;
        H[o] = y;
        Hhi[o] = __float2half_rn(y);
    }
}

// ---------------------------------------------------------------------------
// LayerNorm — 128 threads/row, float4 + warp shuffles
// ---------------------------------------------------------------------------
__global__ __launch_bounds__(128) void ln_kernel(
    const float* __restrict__ in, float* __restrict__ out,
    h16* __restrict__ outHi,
    const float* __restrict__ g, const float* __restrict__ bt)
{
    __shared__ float ws[4], wq[4];
    int row  = blockIdx.x;
    int tid  = threadIdx.x;
    int lane = tid & 31;
    int wd   = tid >> 5;

    float4 v = ((const float4*)(in + (size_t)row * C_))[tid];
    float sum = v.x + v.y + v.z + v.w;
    float sq  = v.x * v.x + v.y * v.y + v.z * v.z + v.w * v.w;
#pragma unroll
    for (int off = 16; off > 0; off >>= 1) {
        sum += __shfl_xor_sync(0xffffffffu, sum, off);
        sq  += __shfl_xor_sync(0xffffffffu, sq,  off);
    }
    if (lane == 0) { ws[wd] = sum; wq[wd] = sq; }
    __syncthreads();
    sum = ws[0] + ws[1] + ws[2] + ws[3];
    sq  = wq[0] + wq[1] + wq[2] + wq[3];

    float mean = sum * (1.f / C_);
    float var  = sq * (1.f / C_) - mean * mean;
    float rstd = rsqrtf(var + 1e-5f);

    float4 gv = ((const float4*)g)[tid];
    float4 bv = ((const float4*)bt)[tid];
    float4 y;
    y.x = (v.x - mean) * rstd * gv.x + bv.x;
    y.y = (v.y - mean) * rstd * gv.y + bv.y;
    y.z = (v.z - mean) * rstd * gv.z + bv.z;
    y.w = (v.w - mean) * rstd * gv.w + bv.w;

    ((float4*)(out + (size_t)row * C_))[tid] = y;
    ((uint2*)(outHi + (size_t)row * C_))[tid] =
        make_uint2(packh2(y.x, y.y), packh2(y.z, y.w));
}

// ---------------------------------------------------------------------------
// Output heads — 4 threads per output, quad shuffle reduce (fp32)
// ---------------------------------------------------------------------------
__global__ __launch_bounds__(256) void heads_kernel(
    const float* __restrict__ H,
    const float* __restrict__ Wps, const float* __restrict__ bps,
    const float* __restrict__ Wpa, const float* __restrict__ bpa,
    float* __restrict__ out)
{
    __shared__ float rows[2 * C_];
    int bt  = blockIdx.x;
    int b   = bt >> 9;
    int t   = bt & 511;
    int tid = threadIdx.x;

    size_t base = ((size_t)(b << 10) + (t << 1)) * C_;
    ((float4*)rows)[tid] = ((const float4*)(H + base))[tid];
    __syncthreads();

    int o   = tid >> 2;
    int sub = tid & 3;
    if (o < SD_ + AD_) {
        const float* w;
        const float* r;
        if (o < SD_) { w = Wps + (size_t)o * C_;          r = rows + C_; }
        else         { w = Wpa + (size_t)(o - SD_) * C_;  r = rows; }
        float a = 0.f;
        int k0 = sub * 128;
#pragma unroll 4
        for (int k = 0; k < 128; k++) a += r[k0 + k] * w[k0 + k];
        a += __shfl_xor_sync(0xffffffffu, a, 1);
        a += __shfl_xor_sync(0xffffffffu, a, 2);
        if (sub == 0) {
            if (o < SD_) out[(size_t)bt * SD_ + o] = a + bps[o];
            else out[(size_t)(B_ * T_ * SD_) + (size_t)bt * AD_ + (o - SD_)] = a + bpa[o - SD_];
        }
    }
}

// ---------------------------------------------------------------------------
// Launch
// ---------------------------------------------------------------------------
extern "C" void kernel_launch(void* const* d_in, const int* in_sizes, int n_in,
                              void* d_out, int out_size)
{
    const float* states  = (const float*)d_in[0];
    const float* actions = (const float*)d_in[1];
    const float* We_s    = (const float*)d_in[2];
    const float* be_s    = (const float*)d_in[3];
    const float* We_a    = (const float*)d_in[4];
    const float* be_a    = (const float*)d_in[5];
    const float* pe      = (const float*)d_in[6];
    const float* g_emb   = (const float*)d_in[7];
    const float* b_emb   = (const float*)d_in[8];
    const float* Wq      = (const float*)d_in[9];
    const float* bq      = (const float*)d_in[10];
    const float* Wk      = (const float*)d_in[11];
    const float* bk      = (const float*)d_in[12];
    const float* Wv      = (const float*)d_in[13];
    const float* bv      = (const float*)d_in[14];
    const float* Wo      = (const float*)d_in[15];
    const float* bo      = (const float*)d_in[16];
    const float* W1      = (const float*)d_in[17];
    const float* b1      = (const float*)d_in[18];
    const float* W2      = (const float*)d_in[19];
    const float* b2      = (const float*)d_in[20];
    const float* g1      = (const float*)d_in[21];
    const float* bt1     = (const float*)d_in[22];
    const float* g2      = (const float*)d_in[23];
    const float* bt2     = (const float*)d_in[24];
    const float* Wps     = (const float*)d_in[25];
    const float* bps     = (const float*)d_in[26];
    const float* Wpa     = (const float*)d_in[27];
    const float* bpa     = (const float*)d_in[28];

    float *H, *tmp;
    h16 *Hhi, *ATThi, *FFhi, *Whi;
    h16 *qhi, *qlo, *khi, *vhi;
    cudaGetSymbolAddress((void**)&H,    g_H);
    cudaGetSymbolAddress((void**)&tmp,  g_tmp);
    cudaGetSymbolAddress((void**)&Hhi,  g_Hhi);
    cudaGetSymbolAddress((void**)&ATThi, g_ATThi);
    cudaGetSymbolAddress((void**)&FFhi, g_FFhi);
    cudaGetSymbolAddress((void**)&Whi,  g_Whi);
    cudaGetSymbolAddress((void**)&qhi,  g_qhi);
    cudaGetSymbolAddress((void**)&qlo,  g_qlo);
    cudaGetSymbolAddress((void**)&khi,  g_khi);
    cudaGetSymbolAddress((void**)&vhi,  g_vhi);

    cudaFuncSetAttribute(tc_gemm_kernel, cudaFuncAttributeMaxDynamicSharedMemorySize, DSMEM_SZ);
    cudaFuncSetAttribute(tc_qkv_kernel,  cudaFuncAttributeMaxDynamicSharedMemorySize, DSMEM_SZ);
    cudaFuncSetAttribute(attn_tc_kernel, cudaFuncAttributeMaxDynamicSharedMemorySize, ATT_SMEM);

    convert6_kernel<<<4096, 256>>>(Wq, Wk, Wv, Wo, W1, W2, Whi);

    embed_kernel<<<MROWS, 256>>>(states, actions, We_s, be_s, We_a, be_a,
                                 pe, g_emb, b_emb, H, Hhi);

    dim3 gC(C_ / 128, MROWS / 128);
    dim3 gF(FF_ / 128, MROWS / 128);
    dim3 gQKV(12, MROWS / 128);

    for (int i = 0; i < L_; i++) {
        size_t wC = (size_t)i * C_ * C_;
        size_t wF = (size_t)i * FF_ * C_;

        tc_qkv_kernel<<<gQKV, 256, DSMEM_SZ>>>(
            Hhi,
            Whi + OW_Q + wC, bq + i * C_,
            Whi + OW_K + wC, bk + i * C_,
            Whi + OW_V + wC, bv + i * C_,
            qhi, qlo, khi, vhi);

        attn_tc_kernel<<<dim3(S_ / 64, B_ * NH_), 128, ATT_SMEM>>>(
            qhi, qlo, khi, vhi, ATThi);

        tc_gemm_kernel<<<gC, 256, DSMEM_SZ>>>(
            ATThi, Whi + OW_O + wC,
            bo + i * C_, H, tmp, nullptr, nullptr, C_, C_, 0, 0);
        ln_kernel<<<MROWS, 128>>>(tmp, H, Hhi, g1 + i * C_, bt1 + i * C_);

        tc_gemm_kernel<<<gF, 256, DSMEM_SZ>>>(
            Hhi, Whi + OW_1 + wF,
            b1 + i * FF_, nullptr, nullptr, FFhi, nullptr, FF_, C_, 1, 0);

        tc_gemm_kernel<<<gC, 256, DSMEM_SZ>>>(
            FFhi, Whi + OW_2 + wF,
            b2 + i * C_, H, tmp, nullptr, nullptr, C_, FF_, 0, 0);
        ln_kernel<<<MROWS, 128>>>(tmp, H, Hhi, g2 + i * C_, bt2 + i * C_);
    }

    heads_kernel<<<B_ * T_, 256>>>(H, Wps, bps, Wpa, bpa, (float*)d_out);
}

// round 14
// speedup vs baseline: 1.6466x; 1.0206x over previous
#include <cuda_runtime.h>
#include <cuda_fp16.h>
#include <math.h>
#include <stdint.h>

// Problem constants
#define B_     8
#define T_     512
#define C_     512
#define L_     4
#define NH_    8
#define DH_    64
#define S_     1024
#define MROWS  8192
#define FF_    2048
#define SD_    48
#define AD_    12

typedef __half h16;

// ---------------------------------------------------------------------------
// Static scratch
// ---------------------------------------------------------------------------
__device__ float g_H  [MROWS * C_];
__device__ float g_tmp[MROWS * C_];

__device__ h16 g_Hhi [MROWS * C_];
__device__ h16 g_ATThi[MROWS * C_];
__device__ h16 g_FFhi[MROWS * FF_];

__device__ h16 g_qhi[MROWS * C_], g_qlo[MROWS * C_];
__device__ h16 g_khi[MROWS * C_];
__device__ h16 g_vhi[MROWS * C_];

#define OW_Q 0
#define OW_K (L_ * C_ * C_)
#define OW_V (2 * L_ * C_ * C_)
#define OW_O (3 * L_ * C_ * C_)
#define OW_1 (4 * L_ * C_ * C_)
#define OW_2 (4 * L_ * C_ * C_ + L_ * FF_ * C_)
#define WTOT (4 * L_ * C_ * C_ + 2 * L_ * FF_ * C_)
__device__ h16 g_Whi[WTOT];

// ---------------------------------------------------------------------------
// PTX helpers (sm_80-era, valid on plain sm_100 target)
// ---------------------------------------------------------------------------
__device__ __forceinline__ uint32_t smem_u32(const void* p) {
    uint32_t a;
    asm("{ .reg .u64 t; cvta.to.shared.u64 t, %1; cvt.u32.u64 %0, t; }"
        : "=r"(a) : "l"(p));
    return a;
}

#define CP16(dst, src) \
    asm volatile("cp.async.cg.shared.global [%0], [%1], 16;" \
                 :: "r"(dst), "l"(src) : "memory")
#define CP_COMMIT()  asm volatile("cp.async.commit_group;" ::: "memory")
#define CP_WAIT1()   asm volatile("cp.async.wait_group 1;" ::: "memory")
#define CP_WAIT0()   asm volatile("cp.async.wait_group 0;" ::: "memory")

#define LDM_X4(r0, r1, r2, r3, addr) \
    asm volatile("ldmatrix.sync.aligned.m8n8.x4.shared.b16 {%0,%1,%2,%3}, [%4];" \
                 : "=r"(r0), "=r"(r1), "=r"(r2), "=r"(r3) : "r"(addr))

#define LDM_X4_T(r0, r1, r2, r3, addr) \
    asm volatile("ldmatrix.sync.aligned.m8n8.x4.trans.shared.b16 {%0,%1,%2,%3}, [%4];" \
                 : "=r"(r0), "=r"(r1), "=r"(r2), "=r"(r3) : "r"(addr))

#define MMA_F16(c, a, b) \
    asm volatile("mma.sync.aligned.m16n8k16.row.col.f32.f16.f16.f32 " \
                 "{%0,%1,%2,%3}, {%4,%5,%6,%7}, {%8,%9}, {%0,%1,%2,%3};" \
                 : "+f"((c)[0]), "+f"((c)[1]), "+f"((c)[2]), "+f"((c)[3]) \
                 : "r"((a)[0]), "r"((a)[1]), "r"((a)[2]), "r"((a)[3]), \
                   "r"((b)[0]), "r"((b)[1]))

__device__ __forceinline__ void split2(float v, h16& h, h16& l) {
    h = __float2half_rn(v);
    l = __float2half_rn(v - __half2float(h));
}

__device__ __forceinline__ void packsplit(float a, float b, uint32_t& ph, uint32_t& pl) {
    __half2 h2, l2;
    h16 ha, la, hb, lb;
    split2(a, ha, la); split2(b, hb, lb);
    h2.x = ha; h2.y = hb; l2.x = la; l2.y = lb;
    ph = *(uint32_t*)&h2; pl = *(uint32_t*)&l2;
}

__device__ __forceinline__ uint32_t packh2(float a, float b) {
    __half2 h2;
    h2.x = __float2half_rn(a); h2.y = __float2half_rn(b);
    return *(uint32_t*)&h2;
}

// ---------------------------------------------------------------------------
// Merged fp32 -> fp16 converter for all six weight groups
// ---------------------------------------------------------------------------
#define CS_Q (L_ * C_ * C_ / 4)
#define CS_W1 (L_ * FF_ * C_ / 4)
#define CTOT4 (4 * CS_Q + 2 * CS_W1)

__global__ __launch_bounds__(256) void convert6_kernel(
    const float* __restrict__ Wq, const float* __restrict__ Wk,
    const float* __restrict__ Wv, const float* __restrict__ Wo,
    const float* __restrict__ W1, const float* __restrict__ W2,
    h16* __restrict__ hi)
{
    for (int i = blockIdx.x * 256 + threadIdx.x; i < CTOT4; i += gridDim.x * 256) {
        const float* src;
        int li;
        if      (i < CS_Q)      { src = Wq; li = i; }
        else if (i < 2 * CS_Q)  { src = Wk; li = i - CS_Q; }
        else if (i < 3 * CS_Q)  { src = Wv; li = i - 2 * CS_Q; }
        else if (i < 4 * CS_Q)  { src = Wo; li = i - 3 * CS_Q; }
        else if (i < 4 * CS_Q + CS_W1) { src = W1; li = i - 4 * CS_Q; }
        else                    { src = W2; li = i - 4 * CS_Q - CS_W1; }
        float4 v = ((const float4*)src)[li];
        ((uint2*)hi)[i] = make_uint2(packh2(v.x, v.y), packh2(v.z, v.w));
    }
}

// ---------------------------------------------------------------------------
// Tensor-core GEMM:  out = A[M,K] @ W[Nn,K]^T, single fp16, 1 MMA per acc.
// BM=BN=128, BK=64, 256 threads, warp grid 4(m) x 2(n), 2 CTAs/SM.
// ---------------------------------------------------------------------------
#define RS_B    144                 // 64 h16 = 128B data + 16B pad
#define TILE_B  (128 * RS_B)        // 18432
#define STAGE_B (2 * TILE_B)        // A, W: 36864
#define DSMEM_SZ (2 * STAGE_B)      // 73728

__device__ __forceinline__ void issue_stage(
    const h16* __restrict__ Ah, const h16* __restrict__ Bh,
    int m0, int n0, int K, int k0, uint32_t sstage, int tid)
{
#pragma unroll
    for (int it = 0; it < 8; it++) {
        int id  = tid + it * 256;          // 0..2047
        int mat = id >> 10;
        int rem = id & 1023;
        int r   = rem >> 3;
        int c   = rem & 7;
        const h16* src = mat ? Bh : Ah;
        int rowbase = mat ? n0 : m0;
        const h16* gp = src + (size_t)(rowbase + r) * K + k0 + c * 8;
        uint32_t dst = sstage + mat * TILE_B + r * RS_B + c * 16;
        CP16(dst, gp);
    }
    CP_COMMIT();
}

__device__ __forceinline__ void tc_gemm_body(
    const h16* __restrict__ Ah, const h16* __restrict__ Bh,
    const float* __restrict__ bias, const float* __restrict__ resid,
    float* __restrict__ outF, h16* __restrict__ outHi, h16* __restrict__ outLo,
    int Nn, int K, int gelu, int headLayout, float oscale, int bx, int by)
{
    extern __shared__ char dsm[];
    uint32_t sbase = smem_u32(dsm);

    int tid  = threadIdx.x;
    int lane = tid & 31;
    int wid  = tid >> 5;
    int wm0  = (wid & 3) * 32;
    int wn0  = (wid >> 2) * 64;
    int m0   = by * 128;
    int n0   = bx * 128;

    float acc[2][8][4];
#pragma unroll
    for (int mt = 0; mt < 2; mt++)
#pragma unroll
        for (int nf = 0; nf < 8; nf++)
#pragma unroll
            for (int e = 0; e < 4; e++) acc[mt][nf][e] = 0.f;

    int S = K >> 6;

    issue_stage(Ah, Bh, m0, n0, K, 0, sbase, tid);

    int aRow = wm0 + (lane & 15);
    int aColB = ((lane >> 4) * 8) * 2;
    int bRowOff = (lane & 7) + ((lane >> 4) << 3);
    int bColB = (((lane >> 3) & 1) * 8) * 2;

    for (int s = 0; s < S; s++) {
        if (s + 1 < S) {
            issue_stage(Ah, Bh, m0, n0, K, (s + 1) << 6,
                        sbase + ((s + 1) & 1) * STAGE_B, tid);
            CP_WAIT1();
        } else {
            CP_WAIT0();
        }
        __syncthreads();

        uint32_t st  = sbase + (s & 1) * STAGE_B;
        uint32_t sAh = st;
        uint32_t sBh = st + TILE_B;

#pragma unroll
        for (int kk = 0; kk < 4; kk++) {
            uint32_t kByte = kk * 32;

            uint32_t ah[2][4];
#pragma unroll
            for (int mt = 0; mt < 2; mt++) {
                uint32_t addr = sAh + (aRow + mt * 16) * RS_B + kByte + aColB;
                LDM_X4(ah[mt][0], ah[mt][1], ah[mt][2], ah[mt][3], addr);
            }

#pragma unroll
            for (int nt = 0; nt < 4; nt++) {
                uint32_t bh0[2], bh1[2];
                uint32_t addr = sBh + (wn0 + nt * 16 + bRowOff) * RS_B + kByte + bColB;
                LDM_X4(bh0[0], bh0[1], bh1[0], bh1[1], addr);
#pragma unroll
                for (int mt = 0; mt < 2; mt++) {
                    MMA_F16(acc[mt][2 * nt],     ah[mt], bh0);
                    MMA_F16(acc[mt][2 * nt + 1], ah[mt], bh1);
                }
            }
        }
        __syncthreads();
    }

    // epilogue
#pragma unroll
    for (int mt = 0; mt < 2; mt++) {
#pragma unroll
        for (int rr = 0; rr < 2; rr++) {
            int m = m0 + wm0 + mt * 16 + (lane >> 2) + rr * 8;
#pragma unroll
            for (int nf = 0; nf < 8; nf++) {
                int c0 = n0 + wn0 + nf * 8 + (lane & 3) * 2;
                float v0 = (acc[mt][nf][rr * 2 + 0] + bias[c0]) * oscale;
                float v1 = (acc[mt][nf][rr * 2 + 1] + bias[c0 + 1]) * oscale;
                if (resid) {
                    const float2 rv = *(const float2*)(resid + (size_t)m * Nn + c0);
                    v0 += rv.x; v1 += rv.y;
                }
                if (gelu) {
                    v0 = 0.5f * v0 * (1.f + erff(v0 * 0.70710678118654752f));
                    v1 = 0.5f * v1 * (1.f + erff(v1 * 0.70710678118654752f));
                }
                size_t off;
                if (headLayout) {
                    int bb = m >> 10, sR = m & 1023, hd = c0 >> 6, d0 = c0 & 63;
                    off = (((size_t)(bb * NH_ + hd) * S_) + sR) * DH_ + d0;
                } else {
                    off = (size_t)m * Nn + c0;
                }
                if (outF) {
                    *(float2*)(outF + off) = make_float2(v0, v1);
                } else if (outLo) {
                    uint32_t ph, pl;
                    packsplit(v0, v1, ph, pl);
                    *(uint32_t*)(outHi + off) = ph;
                    *(uint32_t*)(outLo + off) = pl;
                } else {
                    *(uint32_t*)(outHi + off) = packh2(v0, v1);
                }
            }
        }
    }
}

__global__ __launch_bounds__(256, 2) void tc_gemm_kernel(
    const h16* Ah, const h16* Bh,
    const float* bias, const float* resid,
    float* outF, h16* outHi, h16* outLo,
    int Nn, int K, int gelu, int headLayout)
{
    tc_gemm_body(Ah, Bh, bias, resid, outF, outHi, outLo,
                 Nn, K, gelu, headLayout, 1.0f, blockIdx.x, blockIdx.y);
}

// Fused Q/K/V: grid.x = 12; q split (scaled 0.125), k/v single, head layout.
__global__ __launch_bounds__(256, 2) void tc_qkv_kernel(
    const h16* Ah,
    const h16* Wqh, const float* bq,
    const h16* Wkh, const float* bk,
    const h16* Wvh, const float* bv,
    h16* qhi, h16* qlo, h16* khi, h16* vhi)
{
    int which = blockIdx.x >> 2;
    int bx    = blockIdx.x & 3;
    const h16* Bh   = (which == 0) ? Wqh : (which == 1) ? Wkh : Wvh;
    const float* bi = (which == 0) ? bq  : (which == 1) ? bk  : bv;
    h16* oh         = (which == 0) ? qhi : (which == 1) ? khi : vhi;
    h16* ol         = (which == 0) ? qlo : nullptr;
    float sc        = (which == 0) ? 0.125f : 1.0f;
    tc_gemm_body(Ah, Bh, bi, nullptr, nullptr, oh, ol,
                 C_, C_, 0, 1, sc, bx, blockIdx.y);
}

// ---------------------------------------------------------------------------
// Tensor-core causal flash attention: 64x64 tiles, 128 threads, 4 CTAs/SM.
// Q split fp16, K/V single fp16, P split.  smem: Qh, Ql, Kh, Vh.
// ---------------------------------------------------------------------------
#define RSA_B  144
#define AT_QH  0
#define AT_QL  (64 * RSA_B)
#define AT_KH  (2 * 64 * RSA_B)
#define AT_VH  (3 * 64 * RSA_B)
#define ATT_SMEM (4 * 64 * RSA_B)   // 36864

__global__ __launch_bounds__(128, 4) void attn_tc_kernel(
    const h16* __restrict__ Qhi, const h16* __restrict__ Qlo,
    const h16* __restrict__ Khi, const h16* __restrict__ Vhi,
    h16* __restrict__ attHi)
{
    extern __shared__ char sm[];
    uint32_t sb = smem_u32(sm);

    int tid  = threadIdx.x;
    int lane = tid & 31;
    int wid  = tid >> 5;
    int head = blockIdx.y;
    int q0   = blockIdx.x * 64;
    size_t base = (size_t)head * S_ * DH_;

    {
        int arr = tid & 1, r = tid >> 1;
        const uint4* gq = (const uint4*)((arr ? Qlo : Qhi) + base + (size_t)(q0 + r) * DH_);
        uint4* sq = (uint4*)(sm + (arr ? AT_QL : AT_QH) + r * RSA_B);
#pragma unroll
        for (int e = 0; e < 8; e++) sq[e] = gq[e];
    }
    __syncthreads();

    int aRow = (lane & 15);
    int aCol = (lane >> 4) * 16;
    uint32_t qh[4][4], ql[4][4];
#pragma unroll
    for (int kc = 0; kc < 4; kc++) {
        uint32_t addr = sb + AT_QH + (wid * 16 + aRow) * RSA_B + kc * 32 + aCol;
        LDM_X4(qh[kc][0], qh[kc][1], qh[kc][2], qh[kc][3], addr);
        addr = sb + AT_QL + (wid * 16 + aRow) * RSA_B + kc * 32 + aCol;
        LDM_X4(ql[kc][0], ql[kc][1], ql[kc][2], ql[kc][3], addr);
    }

    int bRow = (lane & 7) + ((lane >> 4) << 3);
    int bCol = ((lane >> 3) & 1) * 16;
    int vRow = (lane & 7) + (((lane >> 3) & 1) << 3);
    int vCol = (lane >> 4) * 16;

    float oa[8][4];
#pragma unroll
    for (int f = 0; f < 8; f++)
#pragma unroll
        for (int e = 0; e < 4; e++) oa[f][e] = 0.f;
    float m0r = -1e30f, m1r = -1e30f, l0r = 0.f, l1r = 0.f;

    int nTiles = blockIdx.x + 1;
    for (int kt = 0; kt < nTiles; kt++) {
        int k0 = kt * 64;
        __syncthreads();
        {
            int arr = tid & 1, r = tid >> 1;
            const uint4* gp = (const uint4*)((arr ? Vhi : Khi) + base + (size_t)(k0 + r) * DH_);
            uint4* sp = (uint4*)(sm + (arr ? AT_VH : AT_KH) + r * RSA_B);
#pragma unroll
            for (int e = 0; e < 8; e++) sp[e] = gp[e];
        }
        __syncthreads();

        float sc[8][4];
#pragma unroll
        for (int f = 0; f < 8; f++)
#pragma unroll
            for (int e = 0; e < 4; e++) sc[f][e] = 0.f;

#pragma unroll
        for (int kc = 0; kc < 4; kc++) {
#pragma unroll
            for (int ntk = 0; ntk < 4; ntk++) {
                uint32_t bh0[2], bh1[2];
                uint32_t addr = sb + AT_KH + (ntk * 16 + bRow) * RSA_B + kc * 32 + bCol;
                LDM_X4(bh0[0], bh0[1], bh1[0], bh1[1], addr);
                MMA_F16(sc[2 * ntk],     qh[kc], bh0);
                MMA_F16(sc[2 * ntk],     ql[kc], bh0);
                MMA_F16(sc[2 * ntk + 1], qh[kc], bh1);
                MMA_F16(sc[2 * ntk + 1], ql[kc], bh1);
            }
        }

        if (kt == nTiles - 1) {
            int rg = q0 + wid * 16 + (lane >> 2);
#pragma unroll
            for (int f = 0; f < 8; f++) {
                int c = k0 + f * 8 + (lane & 3) * 2;
                if (c     > rg)     sc[f][0] = -1e30f;
                if (c + 1 > rg)     sc[f][1] = -1e30f;
                if (c     > rg + 8) sc[f][2] = -1e30f;
                if (c + 1 > rg + 8) sc[f][3] = -1e30f;
            }
        }

        float mx0 = -1e30f, mx1 = -1e30f;
#pragma unroll
        for (int f = 0; f < 8; f++) {
            mx0 = fmaxf(mx0, fmaxf(sc[f][0], sc[f][1]));
            mx1 = fmaxf(mx1, fmaxf(sc[f][2], sc[f][3]));
        }
        mx0 = fmaxf(mx0, __shfl_xor_sync(0xffffffffu, mx0, 1));
        mx0 = fmaxf(mx0, __shfl_xor_sync(0xffffffffu, mx0, 2));
        mx1 = fmaxf(mx1, __shfl_xor_sync(0xffffffffu, mx1, 1));
        mx1 = fmaxf(mx1, __shfl_xor_sync(0xffffffffu, mx1, 2));
        float mn0 = fmaxf(m0r, mx0);
        float mn1 = fmaxf(m1r, mx1);

        float sum0 = 0.f, sum1 = 0.f;
#pragma unroll
        for (int f = 0; f < 8; f++) {
            sc[f][0] = __expf(sc[f][0] - mn0);
            sc[f][1] = __expf(sc[f][1] - mn0);
            sc[f][2] = __expf(sc[f][2] - mn1);
            sc[f][3] = __expf(sc[f][3] - mn1);
            sum0 += sc[f][0] + sc[f][1];
            sum1 += sc[f][2] + sc[f][3];
        }
        sum0 += __shfl_xor_sync(0xffffffffu, sum0, 1);
        sum0 += __shfl_xor_sync(0xffffffffu, sum0, 2);
        sum1 += __shfl_xor_sync(0xffffffffu, sum1, 1);
        sum1 += __shfl_xor_sync(0xffffffffu, sum1, 2);

        float cr0 = __expf(m0r - mn0);
        float cr1 = __expf(m1r - mn1);
        l0r = l0r * cr0 + sum0;
        l1r = l1r * cr1 + sum1;
        m0r = mn0; m1r = mn1;
#pragma unroll
        for (int f = 0; f < 8; f++) {
            oa[f][0] *= cr0; oa[f][1] *= cr0;
            oa[f][2] *= cr1; oa[f][3] *= cr1;
        }

#pragma unroll
        for (int kc = 0; kc < 4; kc++) {
            uint32_t ph[4], pl[4];
            packsplit(sc[2 * kc][0],     sc[2 * kc][1],     ph[0], pl[0]);
            packsplit(sc[2 * kc][2],     sc[2 * kc][3],     ph[1], pl[1]);
            packsplit(sc[2 * kc + 1][0], sc[2 * kc + 1][1], ph[2], pl[2]);
            packsplit(sc[2 * kc + 1][2], sc[2 * kc + 1][3], ph[3], pl[3]);
#pragma unroll
            for (int nt = 0; nt < 4; nt++) {
                uint32_t vh0[2], vh1[2];
                uint32_t addr = sb + AT_VH + (kc * 16 + vRow) * RSA_B + nt * 32 + vCol;
                LDM_X4_T(vh0[0], vh0[1], vh1[0], vh1[1], addr);
                MMA_F16(oa[2 * nt],     ph, vh0);
                MMA_F16(oa[2 * nt],     pl, vh0);
                MMA_F16(oa[2 * nt + 1], ph, vh1);
                MMA_F16(oa[2 * nt + 1], pl, vh1);
            }
        }
    }

    float inv0 = 1.f / l0r, inv1 = 1.f / l1r;
    int brow = (head >> 3) << 10;
    int ncol = (head & 7) << 6;
    int r0   = q0 + wid * 16 + (lane >> 2);
    size_t off0 = (size_t)(brow + r0) * C_ + ncol + (lane & 3) * 2;
    size_t off1 = off0 + (size_t)8 * C_;
#pragma unroll
    for (int f = 0; f < 8; f++) {
        *(uint32_t*)(attHi + off0 + f * 8) = packh2(oa[f][0] * inv0, oa[f][1] * inv0);
        *(uint32_t*)(attHi + off1 + f * 8) = packh2(oa[f][2] * inv1, oa[f][3] * inv1);
    }
}

// ---------------------------------------------------------------------------
// Embedding + interleave + LayerNorm (fp32 + fp16 out)
// ---------------------------------------------------------------------------
__global__ __launch_bounds__(256) void embed_kernel(
    const float* __restrict__ states, const float* __restrict__ actions,
    const float* __restrict__ We_s, const float* __restrict__ be_s,
    const float* __restrict__ We_a, const float* __restrict__ be_a,
    const float* __restrict__ pe,
    const float* __restrict__ g, const float* __restrict__ bt,
    float* __restrict__ H, h16* __restrict__ Hhi)
{
    __shared__ float xs[SD_];
    __shared__ float rs[256], rq[256];

    int row = blockIdx.x;
    int b   = row >> 10;
    int s   = row & 1023;
    int t   = s >> 1;
    int act = s & 1;
    int tid = threadIdx.x;

    int K            = act ? AD_ : SD_;
    const float* x   = act ? (actions + ((size_t)b * T_ + t) * AD_)
                           : (states  + ((size_t)b * T_ + t) * SD_);
    const float* W   = act ? We_a : We_s;
    const float* bia = act ? be_a : be_s;

    if (tid < K) xs[tid] = x[tid];
    __syncthreads();

    float v[2];
    float sum = 0.f, sumsq = 0.f;
#pragma unroll
    for (int e = 0; e < 2; e++) {
        int c = tid + e * 256;
        float a = bia[c] + pe[t * C_ + c];
        const float* wr = W + (size_t)c * K;
        for (int k = 0; k < K; k++) a += xs[k] * wr[k];
        v[e] = a;
        sum += a; sumsq += a * a;
    }
    rs[tid] = sum; rq[tid] = sumsq;
    __syncthreads();
    for (int off = 128; off > 0; off >>= 1) {
        if (tid < off) { rs[tid] += rs[tid + off]; rq[tid] += rq[tid + off]; }
        __syncthreads();
    }
    float mean = rs[0] * (1.f / C_);
    float var  = rq[0] * (1.f / C_) - mean * mean;
    float rstd = rsqrtf(var + 1e-5f);

#pragma unroll
    for (int e = 0; e < 2; e++) {
        int c = tid + e * 256;
        float y = (v[e] - mean) * rstd * g[c] + bt[c];
        size_t o = (size_t)row * C_ + c;
        H[o] = y;
        Hhi[o] = __float2half_rn(y);
    }
}

// ---------------------------------------------------------------------------
// LayerNorm — 128 threads/row, float4 + warp shuffles
// ---------------------------------------------------------------------------
__global__ __launch_bounds__(128) void ln_kernel(
    const float* __restrict__ in, float* __restrict__ out,
    h16* __restrict__ outHi,
    const float* __restrict__ g, const float* __restrict__ bt)
{
    __shared__ float ws[4], wq[4];
    int row  = blockIdx.x;
    int tid  = threadIdx.x;
    int lane = tid & 31;
    int wd   = tid >> 5;

    float4 v = ((const float4*)(in + (size_t)row * C_))[tid];
    float sum = v.x + v.y + v.z + v.w;
    float sq  = v.x * v.x + v.y * v.y + v.z * v.z + v.w * v.w;
#pragma unroll
    for (int off = 16; off > 0; off >>= 1) {
        sum += __shfl_xor_sync(0xffffffffu, sum, off);
        sq  += __shfl_xor_sync(0xffffffffu, sq,  off);
    }
    if (lane == 0) { ws[wd] = sum; wq[wd] = sq; }
    __syncthreads();
    sum = ws[0] + ws[1] + ws[2] + ws[3];
    sq  = wq[0] + wq[1] + wq[2] + wq[3];

    float mean = sum * (1.f / C_);
    float var  = sq * (1.f / C_) - mean * mean;
    float rstd = rsqrtf(var + 1e-5f);

    float4 gv = ((const float4*)g)[tid];
    float4 bv = ((const float4*)bt)[tid];
    float4 y;
    y.x = (v.x - mean) * rstd * gv.x + bv.x;
    y.y = (v.y - mean) * rstd * gv.y + bv.y;
    y.z = (v.z - mean) * rstd * gv.z + bv.z;
    y.w = (v.w - mean) * rstd * gv.w + bv.w;

    ((float4*)(out + (size_t)row * C_))[tid] = y;
    ((uint2*)(outHi + (size_t)row * C_))[tid] =
        make_uint2(packh2(y.x, y.y), packh2(y.z, y.w));
}

// ---------------------------------------------------------------------------
// Output heads — 4 threads per output, quad shuffle reduce (fp32)
// ---------------------------------------------------------------------------
__global__ __launch_bounds__(256) void heads_kernel(
    const float* __restrict__ H,
    const float* __restrict__ Wps, const float* __restrict__ bps,
    const float* __restrict__ Wpa, const float* __restrict__ bpa,
    float* __restrict__ out)
{
    __shared__ float rows[2 * C_];
    int bt  = blockIdx.x;
    int b   = bt >> 9;
    int t   = bt & 511;
    int tid = threadIdx.x;

    size_t base = ((size_t)(b << 10) + (t << 1)) * C_;
    ((float4*)rows)[tid] = ((const float4*)(H + base))[tid];
    __syncthreads();

    int o   = tid >> 2;
    int sub = tid & 3;
    if (o < SD_ + AD_) {
        const float* w;
        const float* r;
        if (o < SD_) { w = Wps + (size_t)o * C_;          r = rows + C_; }
        else         { w = Wpa + (size_t)(o - SD_) * C_;  r = rows; }
        float a = 0.f;
        int k0 = sub * 128;
#pragma unroll 4
        for (int k = 0; k < 128; k++) a += r[k0 + k] * w[k0 + k];
        a += __shfl_xor_sync(0xffffffffu, a, 1);
        a += __shfl_xor_sync(0xffffffffu, a, 2);
        if (sub == 0) {
            if (o < SD_) out[(size_t)bt * SD_ + o] = a + bps[o];
            else out[(size_t)(B_ * T_ * SD_) + (size_t)bt * AD_ + (o - SD_)] = a + bpa[o - SD_];
        }
    }
}

// ---------------------------------------------------------------------------
// Launch
// ---------------------------------------------------------------------------
extern "C" void kernel_launch(void* const* d_in, const int* in_sizes, int n_in,
                              void* d_out, int out_size)
{
    const float* states  = (const float*)d_in[0];
    const float* actions = (const float*)d_in[1];
    const float* We_s    = (const float*)d_in[2];
    const float* be_s    = (const float*)d_in[3];
    const float* We_a    = (const float*)d_in[4];
    const float* be_a    = (const float*)d_in[5];
    const float* pe      = (const float*)d_in[6];
    const float* g_emb   = (const float*)d_in[7];
    const float* b_emb   = (const float*)d_in[8];
    const float* Wq      = (const float*)d_in[9];
    const float* bq      = (const float*)d_in[10];
    const float* Wk      = (const float*)d_in[11];
    const float* bk      = (const float*)d_in[12];
    const float* Wv      = (const float*)d_in[13];
    const float* bv      = (const float*)d_in[14];
    const float* Wo      = (const float*)d_in[15];
    const float* bo      = (const float*)d_in[16];
    const float* W1      = (const float*)d_in[17];
    const float* b1      = (const float*)d_in[18];
    const float* W2      = (const float*)d_in[19];
    const float* b2      = (const float*)d_in[20];
    const float* g1      = (const float*)d_in[21];
    const float* bt1     = (const float*)d_in[22];
    const float* g2      = (const float*)d_in[23];
    const float* bt2     = (const float*)d_in[24];
    const float* Wps     = (const float*)d_in[25];
    const float* bps     = (const float*)d_in[26];
    const float* Wpa     = (const float*)d_in[27];
    const float* bpa     = (const float*)d_in[28];

    float *H, *tmp;
    h16 *Hhi, *ATThi, *FFhi, *Whi;
    h16 *qhi, *qlo, *khi, *vhi;
    cudaGetSymbolAddress((void**)&H,    g_H);
    cudaGetSymbolAddress((void**)&tmp,  g_tmp);
    cudaGetSymbolAddress((void**)&Hhi,  g_Hhi);
    cudaGetSymbolAddress((void**)&ATThi, g_ATThi);
    cudaGetSymbolAddress((void**)&FFhi, g_FFhi);
    cudaGetSymbolAddress((void**)&Whi,  g_Whi);
    cudaGetSymbolAddress((void**)&qhi,  g_qhi);
    cudaGetSymbolAddress((void**)&qlo,  g_qlo);
    cudaGetSymbolAddress((void**)&khi,  g_khi);
    cudaGetSymbolAddress((void**)&vhi,  g_vhi);

    cudaFuncSetAttribute(tc_gemm_kernel, cudaFuncAttributeMaxDynamicSharedMemorySize, DSMEM_SZ);
    cudaFuncSetAttribute(tc_qkv_kernel,  cudaFuncAttributeMaxDynamicSharedMemorySize, DSMEM_SZ);
    cudaFuncSetAttribute(attn_tc_kernel, cudaFuncAttributeMaxDynamicSharedMemorySize, ATT_SMEM);

    convert6_kernel<<<4096, 256>>>(Wq, Wk, Wv, Wo, W1, W2, Whi);

    embed_kernel<<<MROWS, 256>>>(states, actions, We_s, be_s, We_a, be_a,
                                 pe, g_emb, b_emb, H, Hhi);

    dim3 gC(C_ / 128, MROWS / 128);
    dim3 gF(FF_ / 128, MROWS / 128);
    dim3 gQKV(12, MROWS / 128);

    for (int i = 0; i < L_; i++) {
        size_t wC = (size_t)i * C_ * C_;
        size_t wF = (size_t)i * FF_ * C_;

        tc_qkv_kernel<<<gQKV, 256, DSMEM_SZ>>>(
            Hhi,
            Whi + OW_Q + wC, bq + i * C_,
            Whi + OW_K + wC, bk + i * C_,
            Whi + OW_V + wC, bv + i * C_,
            qhi, qlo, khi, vhi);

        attn_tc_kernel<<<dim3(S_ / 64, B_ * NH_), 128, ATT_SMEM>>>(
            qhi, qlo, khi, vhi, ATThi);

        tc_gemm_kernel<<<gC, 256, DSMEM_SZ>>>(
            ATThi, Whi + OW_O + wC,
            bo + i * C_, H, tmp, nullptr, nullptr, C_, C_, 0, 0);
        ln_kernel<<<MROWS, 128>>>(tmp, H, Hhi, g1 + i * C_, bt1 + i * C_);

        tc_gemm_kernel<<<gF, 256, DSMEM_SZ>>>(
            Hhi, Whi + OW_1 + wF,
            b1 + i * FF_, nullptr, nullptr, FFhi, nullptr, FF_, C_, 1, 0);

        tc_gemm_kernel<<<gC, 256, DSMEM_SZ>>>(
            FFhi, Whi + OW_2 + wF,
            b2 + i * C_, H, tmp, nullptr, nullptr, C_, FF_, 0, 0);
        ln_kernel<<<MROWS, 128>>>(tmp, H, Hhi, g2 + i * C_, bt2 + i * C_);
    }

    heads_kernel<<<B_ * T_, 256>>>(H, Wps, bps, Wpa, bpa, (float*)d_out);
}